// round 1
// baseline (speedup 1.0000x reference)
#include <cuda_runtime.h>
#include <math.h>

#define H    5120
#define NH   128
#define QLR  1536
#define DR   64
#define KVLR 512
#define DV   128
#define DN   128
#define DQ   192
#define BMAX 2
#define KVMAX 2048

// ---------------- scratch (device globals; no allocation allowed) ----------------
__device__ float g_qa[BMAX * QLR];
__device__ float g_q[BMAX * NH * DQ];
__device__ float g_qpe[BMAX * NH * DR];
__device__ float g_qabs[BMAX * NH * KVLR];
__device__ float g_kpe[BMAX * KVMAX * DR];
__device__ float g_scores[BMAX * NH * KVMAX];
__device__ float g_part[4][BMAX * NH * KVLR];
__device__ float g_outv[BMAX * NH * DV];

__device__ __forceinline__ float warp_sum(float v) {
    #pragma unroll
    for (int o = 16; o; o >>= 1) v += __shfl_xor_sync(0xFFFFFFFFu, v, o);
    return v;
}

// ---------------- 1) q_a = hidden @ q_a_w^T (warp per row, both batches) ----------------
__global__ void qa_gemv(const float* __restrict__ hs, const float* __restrict__ w) {
    int row  = blockIdx.x * 8 + (threadIdx.x >> 5);
    int lane = threadIdx.x & 31;
    const float4* wr = (const float4*)(w + (size_t)row * H);
    const float4* x0 = (const float4*)hs;
    const float4* x1 = (const float4*)(hs + H);
    float a0 = 0.f, a1 = 0.f;
    #pragma unroll 4
    for (int c = lane; c < H / 4; c += 32) {
        float4 wv = wr[c];
        float4 v0 = x0[c], v1 = x1[c];
        a0 += wv.x * v0.x + wv.y * v0.y + wv.z * v0.z + wv.w * v0.w;
        a1 += wv.x * v1.x + wv.y * v1.y + wv.z * v1.z + wv.w * v1.w;
    }
    a0 = warp_sum(a0); a1 = warp_sum(a1);
    if (!lane) { g_qa[row] = a0; g_qa[QLR + row] = a1; }
}

// ---------------- 2) RMSNorm(q_a) in place ----------------
__global__ void rmsnorm_k(const float* __restrict__ lnw) {
    int b = blockIdx.x, tid = threadIdx.x;  // 512 threads
    float x[3]; float ss = 0.f;
    #pragma unroll
    for (int i = 0; i < 3; i++) { x[i] = g_qa[b * QLR + tid + i * 512]; ss += x[i] * x[i]; }
    __shared__ float red[512];
    red[tid] = ss; __syncthreads();
    for (int s = 256; s; s >>= 1) { if (tid < s) red[tid] += red[tid + s]; __syncthreads(); }
    float inv = rsqrtf(red[0] / (float)QLR + 1e-6f);
    #pragma unroll
    for (int i = 0; i < 3; i++)
        g_qa[b * QLR + tid + i * 512] = x[i] * inv * lnw[tid + i * 512];
}

// ---------------- 3) q = q_a @ q_b_w^T ----------------
__global__ void qb_gemv(const float* __restrict__ w) {
    int row  = blockIdx.x * 8 + (threadIdx.x >> 5);
    int lane = threadIdx.x & 31;
    const float4* wr = (const float4*)(w + (size_t)row * QLR);
    const float4* x0 = (const float4*)g_qa;
    const float4* x1 = (const float4*)(g_qa + QLR);
    float a0 = 0.f, a1 = 0.f;
    #pragma unroll 4
    for (int c = lane; c < QLR / 4; c += 32) {
        float4 wv = wr[c];
        float4 v0 = x0[c], v1 = x1[c];
        a0 += wv.x * v0.x + wv.y * v0.y + wv.z * v0.z + wv.w * v0.w;
        a1 += wv.x * v1.x + wv.y * v1.y + wv.z * v1.z + wv.w * v1.w;
    }
    a0 = warp_sum(a0); a1 = warp_sum(a1);
    if (!lane) { g_q[row] = a0; g_q[NH * DQ + row] = a1; }
}

// ---------------- 4) RoPE on k_pe cache ----------------
#define LOG2_THETA 13.287712379549449f
__global__ void rope_k_kernel(const float* __restrict__ kpe, int KV) {
    int idx = blockIdx.x * 256 + threadIdx.x;  // pair index
    if (idx >= 2 * KV * (DR / 2)) return;
    int i = idx & 31;
    int k = (idx >> 5) % KV;
    int b = idx / (KV * 32);
    float ifr = exp2f(-LOG2_THETA * (float)(2 * i) / 64.0f);
    float ang = (float)k * ifr;
    float s, c; sincosf(ang, &s, &c);
    size_t base = ((size_t)b * KV + k) * DR + 2 * i;
    float x0 = kpe[base], x1 = kpe[base + 1];
    g_kpe[base]     = x0 * c - x1 * s;
    g_kpe[base + 1] = x0 * s + x1 * c;
}

// ---------------- 5) RoPE on q_pe (position KV-1) ----------------
__global__ void rope_q_kernel(int KV) {
    int idx = blockIdx.x * 256 + threadIdx.x;
    if (idx >= 2 * NH * 32) return;
    int i = idx & 31;
    int h = (idx >> 5) % NH;
    int b = idx / (NH * 32);
    float ifr = exp2f(-LOG2_THETA * (float)(2 * i) / 64.0f);
    float ang = (float)(KV - 1) * ifr;
    float s, c; sincosf(ang, &s, &c);
    float x0 = g_q[b * NH * DQ + h * DQ + DN + 2 * i];
    float x1 = g_q[b * NH * DQ + h * DQ + DN + 2 * i + 1];
    g_qpe[(b * NH + h) * DR + 2 * i]     = x0 * c - x1 * s;
    g_qpe[(b * NH + h) * DR + 2 * i + 1] = x0 * s + x1 * c;
}

// ---------------- 6) q_abs[b,h,c] = sum_d q_nope[b,h,d] * kv_b_w[h*256+d, c] ----------------
__global__ void qabs_kernel(const float* __restrict__ kvb) {
    int h = blockIdx.x;          // 128 blocks
    int c = threadIdx.x;         // 512 threads
    __shared__ float qn[2][DN];
    if (c < 256) qn[c >> 7][c & 127] = g_q[(c >> 7) * NH * DQ + h * DQ + (c & 127)];
    __syncthreads();
    const float* wp = kvb + (size_t)(h * 256) * KVLR + c;
    float a0 = 0.f, a1 = 0.f;
    #pragma unroll 8
    for (int d = 0; d < DN; d++) {
        float w = wp[(size_t)d * KVLR];
        a0 += qn[0][d] * w;
        a1 += qn[1][d] * w;
    }
    g_qabs[h * KVLR + c] = a0;
    g_qabs[NH * KVLR + h * KVLR + c] = a1;
}

// ---------------- 7) scores[b,h,k] = (q_abs·c_kv + q_pe·k_pe) * scale ----------------
// block tile: 32 heads x 128 k.  grid (KV/128, 4, B)
__global__ void scores_kernel(const float* __restrict__ ckv, int KV) {
    __shared__ float Qs[32][65];
    __shared__ float Ks[128][65];
    int b = blockIdx.z, h0 = blockIdx.y * 32, k0 = blockIdx.x * 128;
    int tid = threadIdx.x, lane = tid & 31, wid = tid >> 5;
    float acc[4][4] = {};
    for (int chunk = 0; chunk < 9; chunk++) {
        if (chunk < 8) {
            int c0 = chunk * 64;
            for (int t = tid; t < 32 * 16; t += 256) {
                int r = t >> 4, c4 = t & 15;
                float4 v = *(const float4*)&g_qabs[((b * NH) + h0 + r) * KVLR + c0 + c4 * 4];
                Qs[r][c4*4+0] = v.x; Qs[r][c4*4+1] = v.y; Qs[r][c4*4+2] = v.z; Qs[r][c4*4+3] = v.w;
            }
            for (int t = tid; t < 128 * 16; t += 256) {
                int r = t >> 4, c4 = t & 15;
                float4 v = *(const float4*)&ckv[((size_t)b * KV + k0 + r) * KVLR + c0 + c4 * 4];
                Ks[r][c4*4+0] = v.x; Ks[r][c4*4+1] = v.y; Ks[r][c4*4+2] = v.z; Ks[r][c4*4+3] = v.w;
            }
        } else {
            for (int t = tid; t < 32 * 16; t += 256) {
                int r = t >> 4, c4 = t & 15;
                float4 v = *(const float4*)&g_qpe[((b * NH) + h0 + r) * DR + c4 * 4];
                Qs[r][c4*4+0] = v.x; Qs[r][c4*4+1] = v.y; Qs[r][c4*4+2] = v.z; Qs[r][c4*4+3] = v.w;
            }
            for (int t = tid; t < 128 * 16; t += 256) {
                int r = t >> 4, c4 = t & 15;
                float4 v = *(const float4*)&g_kpe[((size_t)b * KV + k0 + r) * DR + c4 * 4];
                Ks[r][c4*4+0] = v.x; Ks[r][c4*4+1] = v.y; Ks[r][c4*4+2] = v.z; Ks[r][c4*4+3] = v.w;
            }
        }
        __syncthreads();
        int nc = (chunk < 8) ? 64 : 64;
        #pragma unroll 8
        for (int cc = 0; cc < nc; cc++) {
            float qv[4], kv4[4];
            #pragma unroll
            for (int i = 0; i < 4; i++) qv[i] = Qs[wid + 8 * i][cc];
            #pragma unroll
            for (int j = 0; j < 4; j++) kv4[j] = Ks[lane + 32 * j][cc];
            #pragma unroll
            for (int i = 0; i < 4; i++)
                #pragma unroll
                for (int j = 0; j < 4; j++)
                    acc[i][j] += qv[i] * kv4[j];
        }
        __syncthreads();
    }
    const float sc = rsqrtf((float)DQ);
    #pragma unroll
    for (int i = 0; i < 4; i++)
        #pragma unroll
        for (int j = 0; j < 4; j++)
            g_scores[(size_t)(b * NH + h0 + wid + 8 * i) * KV + k0 + lane + 32 * j] = acc[i][j] * sc;
}

// ---------------- 8) softmax over k ----------------
__global__ void softmax_kernel(int KV) {
    int bh = blockIdx.x;
    float* s = g_scores + (size_t)bh * KV;
    int tid = threadIdx.x;  // 256
    int n = KV >> 8;        // per-thread count (8 for KV=2048)
    float v[8];
    float m = -1e30f;
    for (int i = 0; i < n; i++) { v[i] = s[tid + i * 256]; m = fmaxf(m, v[i]); }
    __shared__ float red[256];
    red[tid] = m; __syncthreads();
    for (int st = 128; st; st >>= 1) { if (tid < st) red[tid] = fmaxf(red[tid], red[tid + st]); __syncthreads(); }
    m = red[0]; __syncthreads();
    float sum = 0.f;
    for (int i = 0; i < n; i++) { v[i] = __expf(v[i] - m); sum += v[i]; }
    red[tid] = sum; __syncthreads();
    for (int st = 128; st; st >>= 1) { if (tid < st) red[tid] += red[tid + st]; __syncthreads(); }
    float inv = 1.f / red[0];
    for (int i = 0; i < n; i++) s[tid + i * 256] = v[i] * inv;
}

// ---------------- 9) partial attn·c_kv (split-K = 4) ----------------
// block tile: 32 heads x 128 c over KV/4 keys.  grid (4, 4, B*4)
__global__ void actv_kernel(const float* __restrict__ ckv, int KV) {
    __shared__ float As[32][68];
    __shared__ float Bs[64][128];
    int c0 = blockIdx.x * 128, h0 = blockIdx.y * 32;
    int b = blockIdx.z >> 2, sp = blockIdx.z & 3;
    int kbeg = sp * (KV / 4);
    int tid = threadIdx.x, lane = tid & 31, wid = tid >> 5;
    float4 acc[4];
    #pragma unroll
    for (int i = 0; i < 4; i++) acc[i] = make_float4(0.f, 0.f, 0.f, 0.f);
    for (int kc0 = kbeg; kc0 < kbeg + KV / 4; kc0 += 64) {
        for (int t = tid; t < 32 * 16; t += 256) {
            int r = t >> 4, c4 = t & 15;
            float4 v = *(const float4*)&g_scores[(size_t)(b * NH + h0 + r) * KV + kc0 + c4 * 4];
            *(float4*)&As[r][c4 * 4] = v;
        }
        for (int t = tid; t < 64 * 32; t += 256) {
            int r = t >> 5, c4 = t & 31;
            *(float4*)&Bs[r][c4 * 4] =
                *(const float4*)&ckv[((size_t)b * KV + kc0 + r) * KVLR + c0 + c4 * 4];
        }
        __syncthreads();
        #pragma unroll 8
        for (int kc = 0; kc < 64; kc++) {
            float4 bv = *(const float4*)&Bs[kc][lane * 4];
            #pragma unroll
            for (int i = 0; i < 4; i++) {
                float a = As[wid + 8 * i][kc];
                acc[i].x += a * bv.x; acc[i].y += a * bv.y;
                acc[i].z += a * bv.z; acc[i].w += a * bv.w;
            }
        }
        __syncthreads();
    }
    #pragma unroll
    for (int i = 0; i < 4; i++)
        *(float4*)&g_part[sp][(size_t)(b * NH + h0 + wid + 8 * i) * KVLR + c0 + lane * 4] = acc[i];
}

// ---------------- 10) out_v[b,h,dv] = sum_c (attn·c_kv)[b,h,c] * W_v[h,dv,c] ----------------
__global__ void outv_kernel(const float* __restrict__ kvb) {
    int h = blockIdx.x;               // 128 blocks
    __shared__ float as[2 * KVLR];    // [b][c]
    int tid = threadIdx.x;            // 256
    for (int t = tid; t < 2 * KVLR; t += 256) {
        int b = t >> 9, c = t & 511;
        float v = 0.f;
        #pragma unroll
        for (int sp = 0; sp < 4; sp++) v += g_part[sp][(size_t)(b * NH + h) * KVLR + c];
        as[t] = v;
    }
    __syncthreads();
    int lane = tid & 31, wid = tid >> 5;
    for (int r = 0; r < 16; r++) {
        int dv = wid * 16 + r;
        const float4* wp = (const float4*)(kvb + (size_t)(h * 256 + 128 + dv) * KVLR);
        float a0 = 0.f, a1 = 0.f;
        #pragma unroll 4
        for (int c4 = lane; c4 < KVLR / 4; c4 += 32) {
            float4 w = wp[c4];
            int c = c4 * 4;
            a0 += w.x * as[c] + w.y * as[c + 1] + w.z * as[c + 2] + w.w * as[c + 3];
            a1 += w.x * as[512 + c] + w.y * as[512 + c + 1] + w.z * as[512 + c + 2] + w.w * as[512 + c + 3];
        }
        a0 = warp_sum(a0); a1 = warp_sum(a1);
        if (!lane) {
            g_outv[h * DV + dv] = a0;
            g_outv[NH * DV + h * DV + dv] = a1;
        }
    }
}

// ---------------- 11) final = out_v @ o_w^T ----------------
__global__ void oproj_kernel(const float* __restrict__ ow, float* __restrict__ out) {
    int row  = blockIdx.x * 8 + (threadIdx.x >> 5);
    int lane = threadIdx.x & 31;
    const float4* wr = (const float4*)(ow + (size_t)row * (NH * DV));
    const float4* x0 = (const float4*)g_outv;
    const float4* x1 = (const float4*)(g_outv + NH * DV);
    float a0 = 0.f, a1 = 0.f;
    #pragma unroll 4
    for (int c = lane; c < (NH * DV) / 4; c += 32) {
        float4 wv = wr[c];
        float4 v0 = x0[c], v1 = x1[c];
        a0 += wv.x * v0.x + wv.y * v0.y + wv.z * v0.z + wv.w * v0.w;
        a1 += wv.x * v1.x + wv.y * v1.y + wv.z * v1.z + wv.w * v1.w;
    }
    a0 = warp_sum(a0); a1 = warp_sum(a1);
    if (!lane) { out[row] = a0; out[H + row] = a1; }
}

// ---------------- launch ----------------
extern "C" void kernel_launch(void* const* d_in, const int* in_sizes, int n_in,
                              void* d_out, int out_size) {
    const float* hidden = (const float*)d_in[0];
    const float* ckv    = (const float*)d_in[1];
    const float* kpe    = (const float*)d_in[2];
    const float* qaw    = (const float*)d_in[3];
    const float* lnw    = (const float*)d_in[4];
    const float* qbw    = (const float*)d_in[5];
    const float* kvb    = (const float*)d_in[6];
    const float* ow     = (const float*)d_in[7];
    float* out = (float*)d_out;

    int B  = in_sizes[0] / H;          // 2
    int KV = in_sizes[2] / (B * DR);   // 2048

    qa_gemv<<<QLR / 8, 256>>>(hidden, qaw);
    rmsnorm_k<<<B, 512>>>(lnw);
    qb_gemv<<<(NH * DQ) / 8, 256>>>(qbw);
    rope_k_kernel<<<(B * KV * 32 + 255) / 256, 256>>>(kpe, KV);
    rope_q_kernel<<<(B * NH * 32 + 255) / 256, 256>>>(KV);
    qabs_kernel<<<NH, 512>>>(kvb);
    scores_kernel<<<dim3(KV / 128, NH / 32, B), 256>>>(ckv, KV);
    softmax_kernel<<<B * NH, 256>>>(KV);
    actv_kernel<<<dim3(KVLR / 128, NH / 32, B * 4), 256>>>(ckv, KV);
    outv_kernel<<<NH, 256>>>(kvb);
    oproj_kernel<<<H / 8, 256>>>(ow, out);
}

// round 2
// speedup vs baseline: 1.0664x; 1.0664x over previous
#include <cuda_runtime.h>
#include <math.h>

#define H    5120
#define NH   128
#define QLR  1536
#define DR   64
#define KVLR 512
#define DV   128
#define DN   128
#define DQ   192
#define BMAX 2
#define KVMAX 2048

// ---------------- scratch (device globals; no allocation allowed) ----------------
__device__ float g_qa[BMAX * QLR];
__device__ float g_q[BMAX * NH * DQ];
__device__ float g_qpe[BMAX * NH * DR];
__device__ float g_qabs[BMAX * NH * KVLR];
__device__ float g_kpe[BMAX * KVMAX * DR];
__device__ float g_scores[BMAX * NH * KVMAX];
__device__ float g_part[4][BMAX * NH * KVLR];
__device__ float g_outv[BMAX * NH * DV];

__device__ __forceinline__ float warp_sum(float v) {
    #pragma unroll
    for (int o = 16; o; o >>= 1) v += __shfl_xor_sync(0xFFFFFFFFu, v, o);
    return v;
}

// ---------------- 1) q_a = hidden @ q_a_w^T (warp per row, both batches) ----------------
__global__ void __launch_bounds__(256) qa_gemv(const float* __restrict__ hs, const float* __restrict__ w) {
    int row  = blockIdx.x * 8 + (threadIdx.x >> 5);
    int lane = threadIdx.x & 31;
    const float4* wr = (const float4*)(w + (size_t)row * H);
    const float4* x0 = (const float4*)hs;
    const float4* x1 = (const float4*)(hs + H);
    float a0 = 0.f, a1 = 0.f;
    #pragma unroll 8
    for (int c = lane; c < H / 4; c += 32) {
        float4 wv = wr[c];
        float4 v0 = x0[c], v1 = x1[c];
        a0 += wv.x * v0.x + wv.y * v0.y + wv.z * v0.z + wv.w * v0.w;
        a1 += wv.x * v1.x + wv.y * v1.y + wv.z * v1.z + wv.w * v1.w;
    }
    a0 = warp_sum(a0); a1 = warp_sum(a1);
    if (!lane) { g_qa[row] = a0; g_qa[QLR + row] = a1; }
}

// ---------------- 2) RMSNorm(q_a) in place ----------------
__global__ void __launch_bounds__(512) rmsnorm_k(const float* __restrict__ lnw) {
    int b = blockIdx.x, tid = threadIdx.x;  // 512 threads
    float x[3]; float ss = 0.f;
    #pragma unroll
    for (int i = 0; i < 3; i++) { x[i] = g_qa[b * QLR + tid + i * 512]; ss += x[i] * x[i]; }
    __shared__ float red[512];
    red[tid] = ss; __syncthreads();
    for (int s = 256; s; s >>= 1) { if (tid < s) red[tid] += red[tid + s]; __syncthreads(); }
    float inv = rsqrtf(red[0] / (float)QLR + 1e-6f);
    #pragma unroll
    for (int i = 0; i < 3; i++)
        g_qa[b * QLR + tid + i * 512] = x[i] * inv * lnw[tid + i * 512];
}

// ---------------- 3) q = q_a @ q_b_w^T ----------------
__global__ void __launch_bounds__(256) qb_gemv(const float* __restrict__ w) {
    int row  = blockIdx.x * 8 + (threadIdx.x >> 5);
    int lane = threadIdx.x & 31;
    const float4* wr = (const float4*)(w + (size_t)row * QLR);
    const float4* x0 = (const float4*)g_qa;
    const float4* x1 = (const float4*)(g_qa + QLR);
    float a0 = 0.f, a1 = 0.f;
    #pragma unroll 8
    for (int c = lane; c < QLR / 4; c += 32) {
        float4 wv = wr[c];
        float4 v0 = x0[c], v1 = x1[c];
        a0 += wv.x * v0.x + wv.y * v0.y + wv.z * v0.z + wv.w * v0.w;
        a1 += wv.x * v1.x + wv.y * v1.y + wv.z * v1.z + wv.w * v1.w;
    }
    a0 = warp_sum(a0); a1 = warp_sum(a1);
    if (!lane) { g_q[row] = a0; g_q[NH * DQ + row] = a1; }
}

// ---------------- 4+5) RoPE on k_pe cache AND q_pe (fast sincos, one kernel) ----------------
#define LOG2_THETA 13.287712379549449f
__global__ void __launch_bounds__(256) rope_all(const float* __restrict__ kpe, int KV) {
    int idx = blockIdx.x * 256 + threadIdx.x;  // pair index
    int nk = 2 * KV * 32;
    if (idx < nk) {
        int i = idx & 31;
        int k = (idx >> 5) % KV;
        int b = idx / (KV * 32);
        float ifr = exp2f(-LOG2_THETA * (float)(2 * i) / 64.0f);
        float s, c; __sincosf((float)k * ifr, &s, &c);
        size_t base = ((size_t)b * KV + k) * DR + 2 * i;
        float x0 = kpe[base], x1 = kpe[base + 1];
        g_kpe[base]     = x0 * c - x1 * s;
        g_kpe[base + 1] = x0 * s + x1 * c;
    } else {
        idx -= nk;
        if (idx >= 2 * NH * 32) return;
        int i = idx & 31;
        int h = (idx >> 5) % NH;
        int b = idx / (NH * 32);
        float ifr = exp2f(-LOG2_THETA * (float)(2 * i) / 64.0f);
        float s, c; __sincosf((float)(KV - 1) * ifr, &s, &c);
        float x0 = g_q[b * NH * DQ + h * DQ + DN + 2 * i];
        float x1 = g_q[b * NH * DQ + h * DQ + DN + 2 * i + 1];
        g_qpe[(b * NH + h) * DR + 2 * i]     = x0 * c - x1 * s;
        g_qpe[(b * NH + h) * DR + 2 * i + 1] = x0 * s + x1 * c;
    }
}

// ---------------- 6) q_abs[b,h,c] = sum_d q_nope[b,h,d] * kv_b_w[h*256+d, c] ----------------
__global__ void __launch_bounds__(512) qabs_kernel(const float* __restrict__ kvb) {
    int h = blockIdx.x;          // 128 blocks
    int c = threadIdx.x;         // 512 threads
    __shared__ float qn[2][DN];
    if (c < 256) qn[c >> 7][c & 127] = g_q[(c >> 7) * NH * DQ + h * DQ + (c & 127)];
    __syncthreads();
    const float* wp = kvb + (size_t)(h * 256) * KVLR + c;
    float a0 = 0.f, a1 = 0.f;
    #pragma unroll 16
    for (int d = 0; d < DN; d++) {
        float w = wp[(size_t)d * KVLR];
        a0 += qn[0][d] * w;
        a1 += qn[1][d] * w;
    }
    g_qabs[h * KVLR + c] = a0;
    g_qabs[NH * KVLR + h * KVLR + c] = a1;
}

// ---------------- 7) scores[b,h,k] = (q_abs·c_kv + q_pe·k_pe) * scale ----------------
// block tile: 32 heads x 128 k.  grid (KV/128, 4, B)  -- FFMA-pipe-bound (fp32 floor)
__global__ void __launch_bounds__(256) scores_kernel(const float* __restrict__ ckv, int KV) {
    __shared__ float Qs[32][65];
    __shared__ float Ks[128][65];
    int b = blockIdx.z, h0 = blockIdx.y * 32, k0 = blockIdx.x * 128;
    int tid = threadIdx.x, lane = tid & 31, wid = tid >> 5;
    float acc[4][4] = {};
    for (int chunk = 0; chunk < 9; chunk++) {
        if (chunk < 8) {
            int c0 = chunk * 64;
            for (int t = tid; t < 32 * 16; t += 256) {
                int r = t >> 4, c4 = t & 15;
                float4 v = *(const float4*)&g_qabs[((b * NH) + h0 + r) * KVLR + c0 + c4 * 4];
                Qs[r][c4*4+0] = v.x; Qs[r][c4*4+1] = v.y; Qs[r][c4*4+2] = v.z; Qs[r][c4*4+3] = v.w;
            }
            for (int t = tid; t < 128 * 16; t += 256) {
                int r = t >> 4, c4 = t & 15;
                float4 v = *(const float4*)&ckv[((size_t)b * KV + k0 + r) * KVLR + c0 + c4 * 4];
                Ks[r][c4*4+0] = v.x; Ks[r][c4*4+1] = v.y; Ks[r][c4*4+2] = v.z; Ks[r][c4*4+3] = v.w;
            }
        } else {
            for (int t = tid; t < 32 * 16; t += 256) {
                int r = t >> 4, c4 = t & 15;
                float4 v = *(const float4*)&g_qpe[((b * NH) + h0 + r) * DR + c4 * 4];
                Qs[r][c4*4+0] = v.x; Qs[r][c4*4+1] = v.y; Qs[r][c4*4+2] = v.z; Qs[r][c4*4+3] = v.w;
            }
            for (int t = tid; t < 128 * 16; t += 256) {
                int r = t >> 4, c4 = t & 15;
                float4 v = *(const float4*)&g_kpe[((size_t)b * KV + k0 + r) * DR + c4 * 4];
                Ks[r][c4*4+0] = v.x; Ks[r][c4*4+1] = v.y; Ks[r][c4*4+2] = v.z; Ks[r][c4*4+3] = v.w;
            }
        }
        __syncthreads();
        #pragma unroll 8
        for (int cc = 0; cc < 64; cc++) {
            float qv[4], kv4[4];
            #pragma unroll
            for (int i = 0; i < 4; i++) qv[i] = Qs[wid + 8 * i][cc];
            #pragma unroll
            for (int j = 0; j < 4; j++) kv4[j] = Ks[lane + 32 * j][cc];
            #pragma unroll
            for (int i = 0; i < 4; i++)
                #pragma unroll
                for (int j = 0; j < 4; j++)
                    acc[i][j] += qv[i] * kv4[j];
        }
        __syncthreads();
    }
    const float sc = rsqrtf((float)DQ);
    #pragma unroll
    for (int i = 0; i < 4; i++)
        #pragma unroll
        for (int j = 0; j < 4; j++)
            g_scores[(size_t)(b * NH + h0 + wid + 8 * i) * KV + k0 + lane + 32 * j] = acc[i][j] * sc;
}

// ---------------- 8) softmax over k ----------------
__global__ void __launch_bounds__(256) softmax_kernel(int KV) {
    int bh = blockIdx.x;
    float* s = g_scores + (size_t)bh * KV;
    int tid = threadIdx.x;  // 256
    int n = KV >> 8;        // per-thread count (8 for KV=2048)
    float v[8];
    float m = -1e30f;
    for (int i = 0; i < n; i++) { v[i] = s[tid + i * 256]; m = fmaxf(m, v[i]); }
    __shared__ float red[256];
    red[tid] = m; __syncthreads();
    for (int st = 128; st; st >>= 1) { if (tid < st) red[tid] = fmaxf(red[tid], red[tid + st]); __syncthreads(); }
    m = red[0]; __syncthreads();
    float sum = 0.f;
    for (int i = 0; i < n; i++) { v[i] = __expf(v[i] - m); sum += v[i]; }
    red[tid] = sum; __syncthreads();
    for (int st = 128; st; st >>= 1) { if (tid < st) red[tid] += red[tid + st]; __syncthreads(); }
    float inv = 1.f / red[0];
    for (int i = 0; i < n; i++) s[tid + i * 256] = v[i] * inv;
}

// ---------------- 9) partial attn·c_kv (split-K = 4) ----------------
// block tile: 32 heads x 128 c over KV/4 keys.  grid (4, 4, B*4)
__global__ void __launch_bounds__(256) actv_kernel(const float* __restrict__ ckv, int KV) {
    __shared__ float As[32][68];
    __shared__ float Bs[64][128];
    int c0 = blockIdx.x * 128, h0 = blockIdx.y * 32;
    int b = blockIdx.z >> 2, sp = blockIdx.z & 3;
    int kbeg = sp * (KV / 4);
    int tid = threadIdx.x, lane = tid & 31, wid = tid >> 5;
    float4 acc[4];
    #pragma unroll
    for (int i = 0; i < 4; i++) acc[i] = make_float4(0.f, 0.f, 0.f, 0.f);
    for (int kc0 = kbeg; kc0 < kbeg + KV / 4; kc0 += 64) {
        for (int t = tid; t < 32 * 16; t += 256) {
            int r = t >> 4, c4 = t & 15;
            float4 v = *(const float4*)&g_scores[(size_t)(b * NH + h0 + r) * KV + kc0 + c4 * 4];
            *(float4*)&As[r][c4 * 4] = v;
        }
        for (int t = tid; t < 64 * 32; t += 256) {
            int r = t >> 5, c4 = t & 31;
            *(float4*)&Bs[r][c4 * 4] =
                *(const float4*)&ckv[((size_t)b * KV + kc0 + r) * KVLR + c0 + c4 * 4];
        }
        __syncthreads();
        #pragma unroll 8
        for (int kc = 0; kc < 64; kc++) {
            float4 bv = *(const float4*)&Bs[kc][lane * 4];
            #pragma unroll
            for (int i = 0; i < 4; i++) {
                float a = As[wid + 8 * i][kc];
                acc[i].x += a * bv.x; acc[i].y += a * bv.y;
                acc[i].z += a * bv.z; acc[i].w += a * bv.w;
            }
        }
        __syncthreads();
    }
    #pragma unroll
    for (int i = 0; i < 4; i++)
        *(float4*)&g_part[sp][(size_t)(b * NH + h0 + wid + 8 * i) * KVLR + c0 + lane * 4] = acc[i];
}

// ---------------- 10) out_v[b,h,dv] = sum_c (attn·c_kv)[b,h,c] * W_v[h,dv,c] ----------------
__global__ void __launch_bounds__(256) outv_kernel(const float* __restrict__ kvb) {
    int h = blockIdx.x;               // 128 blocks
    __shared__ float as[2 * KVLR];    // [b][c]
    int tid = threadIdx.x;            // 256
    for (int t = tid; t < 2 * KVLR; t += 256) {
        int b = t >> 9, c = t & 511;
        float v = 0.f;
        #pragma unroll
        for (int sp = 0; sp < 4; sp++) v += g_part[sp][(size_t)(b * NH + h) * KVLR + c];
        as[t] = v;
    }
    __syncthreads();
    int lane = tid & 31, wid = tid >> 5;
    #pragma unroll 2
    for (int r = 0; r < 16; r++) {
        int dv = wid * 16 + r;
        const float4* wp = (const float4*)(kvb + (size_t)(h * 256 + 128 + dv) * KVLR);
        float a0 = 0.f, a1 = 0.f;
        #pragma unroll 4
        for (int c4 = lane; c4 < KVLR / 4; c4 += 32) {
            float4 w = wp[c4];
            int c = c4 * 4;
            a0 += w.x * as[c] + w.y * as[c + 1] + w.z * as[c + 2] + w.w * as[c + 3];
            a1 += w.x * as[512 + c] + w.y * as[512 + c + 1] + w.z * as[512 + c + 2] + w.w * as[512 + c + 3];
        }
        a0 = warp_sum(a0); a1 = warp_sum(a1);
        if (!lane) {
            g_outv[h * DV + dv] = a0;
            g_outv[NH * DV + h * DV + dv] = a1;
        }
    }
}

// ---------------- 11) final = out_v @ o_w^T ----------------
__global__ void __launch_bounds__(256) oproj_kernel(const float* __restrict__ ow, float* __restrict__ out) {
    int row  = blockIdx.x * 8 + (threadIdx.x >> 5);
    int lane = threadIdx.x & 31;
    const float4* wr = (const float4*)(ow + (size_t)row * (NH * DV));
    const float4* x0 = (const float4*)g_outv;
    const float4* x1 = (const float4*)(g_outv + NH * DV);
    float a0 = 0.f, a1 = 0.f;
    #pragma unroll 8
    for (int c = lane; c < (NH * DV) / 4; c += 32) {
        float4 wv = wr[c];
        float4 v0 = x0[c], v1 = x1[c];
        a0 += wv.x * v0.x + wv.y * v0.y + wv.z * v0.z + wv.w * v0.w;
        a1 += wv.x * v1.x + wv.y * v1.y + wv.z * v1.z + wv.w * v1.w;
    }
    a0 = warp_sum(a0); a1 = warp_sum(a1);
    if (!lane) { out[row] = a0; out[H + row] = a1; }
}

// ---------------- launch ----------------
extern "C" void kernel_launch(void* const* d_in, const int* in_sizes, int n_in,
                              void* d_out, int out_size) {
    const float* hidden = (const float*)d_in[0];
    const float* ckv    = (const float*)d_in[1];
    const float* kpe    = (const float*)d_in[2];
    const float* qaw    = (const float*)d_in[3];
    const float* lnw    = (const float*)d_in[4];
    const float* qbw    = (const float*)d_in[5];
    const float* kvb    = (const float*)d_in[6];
    const float* ow     = (const float*)d_in[7];
    float* out = (float*)d_out;

    int B  = in_sizes[0] / H;          // 2
    int KV = in_sizes[2] / (B * DR);   // 2048

    qa_gemv<<<QLR / 8, 256>>>(hidden, qaw);
    rmsnorm_k<<<B, 512>>>(lnw);
    qb_gemv<<<(NH * DQ) / 8, 256>>>(qbw);
    rope_all<<<(B * KV * 32 + B * NH * 32 + 255) / 256, 256>>>(kpe, KV);
    qabs_kernel<<<NH, 512>>>(kvb);
    scores_kernel<<<dim3(KV / 128, NH / 32, B), 256>>>(ckv, KV);
    softmax_kernel<<<B * NH, 256>>>(KV);
    actv_kernel<<<dim3(KVLR / 128, NH / 32, B * 4), 256>>>(ckv, KV);
    outv_kernel<<<NH, 256>>>(kvb);
    oproj_kernel<<<H / 8, 256>>>(ow, out);
}

// round 3
// speedup vs baseline: 1.1657x; 1.0930x over previous
#include <cuda_runtime.h>
#include <math.h>

#define H    5120
#define NH   128
#define QLR  1536
#define DR   64
#define KVLR 512
#define DV   128
#define DN   128
#define DQ   192
#define BMAX 2
#define KVMAX 2048

// ---------------- scratch (device globals; no allocation allowed) ----------------
__device__ float g_qa[BMAX * QLR];
__device__ float g_q[BMAX * NH * DQ];
__device__ float g_qpe[BMAX * NH * DR];
__device__ float g_qabs[BMAX * NH * KVLR];
__device__ float g_kpe[BMAX * KVMAX * DR];
__device__ float g_scores[BMAX * NH * KVMAX];
__device__ float g_part[4][BMAX * NH * KVLR];
__device__ float g_outv[BMAX * NH * DV];

__device__ __forceinline__ float warp_sum(float v) {
    #pragma unroll
    for (int o = 16; o; o >>= 1) v += __shfl_xor_sync(0xFFFFFFFFu, v, o);
    return v;
}

// ---- packed fp32x2 helpers (sm_100+; SASS FFMA2 -> 2x fp32 MAC rate, bit-exact) ----
__device__ __forceinline__ unsigned long long pack2(float lo, float hi) {
    unsigned long long r;
    asm("mov.b64 %0, {%1, %2};" : "=l"(r) : "f"(lo), "f"(hi));
    return r;
}
__device__ __forceinline__ void unpack2(unsigned long long v, float& lo, float& hi) {
    asm("mov.b64 {%0, %1}, %2;" : "=f"(lo), "=f"(hi) : "l"(v));
}
__device__ __forceinline__ void ffma2(unsigned long long& d, unsigned long long a, unsigned long long b) {
    asm("fma.rn.f32x2 %0, %1, %2, %0;" : "+l"(d) : "l"(a), "l"(b));
}

// ---------------- 1) q_a = hidden @ q_a_w^T (block per row, both batches) ----------------
__global__ void __launch_bounds__(128) qa_gemv(const float* __restrict__ hs, const float* __restrict__ w) {
    int row = blockIdx.x;
    int tid = threadIdx.x;  // 128
    const float4* wr = (const float4*)(w + (size_t)row * H);
    const float4* x0 = (const float4*)hs;
    const float4* x1 = (const float4*)(hs + H);
    float a0 = 0.f, a1 = 0.f;
    #pragma unroll 10
    for (int c = tid; c < H / 4; c += 128) {
        float4 wv = __ldcs(&wr[c]);
        float4 v0 = x0[c], v1 = x1[c];
        a0 += wv.x * v0.x + wv.y * v0.y + wv.z * v0.z + wv.w * v0.w;
        a1 += wv.x * v1.x + wv.y * v1.y + wv.z * v1.z + wv.w * v1.w;
    }
    a0 = warp_sum(a0); a1 = warp_sum(a1);
    __shared__ float r0[4], r1[4];
    int lane = tid & 31, wid = tid >> 5;
    if (!lane) { r0[wid] = a0; r1[wid] = a1; }
    __syncthreads();
    if (tid == 0) g_qa[row]       = r0[0] + r0[1] + r0[2] + r0[3];
    if (tid == 1) g_qa[QLR + row] = r1[0] + r1[1] + r1[2] + r1[3];
}

// ---------------- 2) RMSNorm(q_a) in place ----------------
__global__ void __launch_bounds__(512) rmsnorm_k(const float* __restrict__ lnw) {
    int b = blockIdx.x, tid = threadIdx.x;  // 512 threads
    float x[3]; float ss = 0.f;
    #pragma unroll
    for (int i = 0; i < 3; i++) { x[i] = g_qa[b * QLR + tid + i * 512]; ss += x[i] * x[i]; }
    __shared__ float red[512];
    red[tid] = ss; __syncthreads();
    for (int s = 256; s; s >>= 1) { if (tid < s) red[tid] += red[tid + s]; __syncthreads(); }
    float inv = rsqrtf(red[0] / (float)QLR + 1e-6f);
    #pragma unroll
    for (int i = 0; i < 3; i++)
        g_qa[b * QLR + tid + i * 512] = x[i] * inv * lnw[tid + i * 512];
}

// ---------------- 3) q = q_a @ q_b_w^T ----------------
__global__ void __launch_bounds__(256) qb_gemv(const float* __restrict__ w) {
    int row  = blockIdx.x * 8 + (threadIdx.x >> 5);
    int lane = threadIdx.x & 31;
    const float4* wr = (const float4*)(w + (size_t)row * QLR);
    const float4* x0 = (const float4*)g_qa;
    const float4* x1 = (const float4*)(g_qa + QLR);
    float a0 = 0.f, a1 = 0.f;
    #pragma unroll 8
    for (int c = lane; c < QLR / 4; c += 32) {
        float4 wv = __ldcs(&wr[c]);
        float4 v0 = x0[c], v1 = x1[c];
        a0 += wv.x * v0.x + wv.y * v0.y + wv.z * v0.z + wv.w * v0.w;
        a1 += wv.x * v1.x + wv.y * v1.y + wv.z * v1.z + wv.w * v1.w;
    }
    a0 = warp_sum(a0); a1 = warp_sum(a1);
    if (!lane) { g_q[row] = a0; g_q[NH * DQ + row] = a1; }
}

// ---------------- 4) RoPE on k_pe cache AND q_pe (fast sincos, one kernel) ----------------
#define LOG2_THETA 13.287712379549449f
__global__ void __launch_bounds__(256) rope_all(const float* __restrict__ kpe, int KV) {
    int idx = blockIdx.x * 256 + threadIdx.x;  // pair index
    int nk = 2 * KV * 32;
    if (idx < nk) {
        int i = idx & 31;
        int k = (idx >> 5) % KV;
        int b = idx / (KV * 32);
        float ifr = exp2f(-LOG2_THETA * (float)(2 * i) / 64.0f);
        float s, c; __sincosf((float)k * ifr, &s, &c);
        size_t base = ((size_t)b * KV + k) * DR + 2 * i;
        float x0 = kpe[base], x1 = kpe[base + 1];
        g_kpe[base]     = x0 * c - x1 * s;
        g_kpe[base + 1] = x0 * s + x1 * c;
    } else {
        idx -= nk;
        if (idx >= 2 * NH * 32) return;
        int i = idx & 31;
        int h = (idx >> 5) % NH;
        int b = idx / (NH * 32);
        float ifr = exp2f(-LOG2_THETA * (float)(2 * i) / 64.0f);
        float s, c; __sincosf((float)(KV - 1) * ifr, &s, &c);
        float x0 = g_q[b * NH * DQ + h * DQ + DN + 2 * i];
        float x1 = g_q[b * NH * DQ + h * DQ + DN + 2 * i + 1];
        g_qpe[(b * NH + h) * DR + 2 * i]     = x0 * c - x1 * s;
        g_qpe[(b * NH + h) * DR + 2 * i + 1] = x0 * s + x1 * c;
    }
}

// ---------------- 5) q_abs[b,h,c] = sum_d q_nope[b,h,d] * kv_b_w[h*256+d, c] ----------------
__global__ void __launch_bounds__(512) qabs_kernel(const float* __restrict__ kvb) {
    int h = blockIdx.x;          // 128 blocks
    int c = threadIdx.x;         // 512 threads
    __shared__ float qn[2][DN];
    if (c < 256) qn[c >> 7][c & 127] = g_q[(c >> 7) * NH * DQ + h * DQ + (c & 127)];
    __syncthreads();
    const float* wp = kvb + (size_t)(h * 256) * KVLR + c;
    float a0 = 0.f, a1 = 0.f;
    #pragma unroll 16
    for (int d = 0; d < DN; d++) {
        float w = wp[(size_t)d * KVLR];
        a0 += qn[0][d] * w;
        a1 += qn[1][d] * w;
    }
    g_qabs[h * KVLR + c] = a0;
    g_qabs[NH * KVLR + h * KVLR + c] = a1;
}

// ---------------- 6) scores[b,h,k] = (q_abs·c_kv + q_pe·k_pe) * scale ----------------
// block tile: 32 heads x 128 k.  grid (KV/128, 4, B).  FFMA2-packed inner loop.
__global__ void __launch_bounds__(256) scores_kernel(const float* __restrict__ ckv, int KV) {
    __shared__ float Qs[32][66];     // [h-local][channel in chunk]
    __shared__ float KsT[64][130];   // [channel in chunk][k-local], pad 2 (even -> float2 aligned)
    int b = blockIdx.z, h0 = blockIdx.y * 32, k0 = blockIdx.x * 128;
    int tid = threadIdx.x, lane = tid & 31, wid = tid >> 5;
    // thread owns h = h0 + wid + 8i (i=0..3), k = k0 + lane*2 + 64*jj + {0,1} (jj=0..1)
    unsigned long long acc[4][2] = {};
    for (int chunk = 0; chunk < 9; chunk++) {
        if (chunk < 8) {
            int c0 = chunk * 64;
            // Qs: 32 rows x 64 ch (float4 loads)
            #pragma unroll
            for (int t = tid; t < 32 * 16; t += 256) {
                int r = t >> 4, c4 = t & 15;
                float4 v = *(const float4*)&g_qabs[((b * NH) + h0 + r) * KVLR + c0 + c4 * 4];
                Qs[r][c4*4+0] = v.x; Qs[r][c4*4+1] = v.y; Qs[r][c4*4+2] = v.z; Qs[r][c4*4+3] = v.w;
            }
            // KsT transpose load: thread -> (c = tid&63, kk = tid>>6), loop over k groups of 4
            int c = tid & 63, kk = tid >> 6;
            #pragma unroll 8
            for (int kq = 0; kq < 32; kq++) {
                int k = kq * 4 + kk;
                KsT[c][k] = ckv[((size_t)b * KV + k0 + k) * KVLR + c0 + c];
            }
        } else {
            #pragma unroll
            for (int t = tid; t < 32 * 16; t += 256) {
                int r = t >> 4, c4 = t & 15;
                float4 v = *(const float4*)&g_qpe[((b * NH) + h0 + r) * DR + c4 * 4];
                Qs[r][c4*4+0] = v.x; Qs[r][c4*4+1] = v.y; Qs[r][c4*4+2] = v.z; Qs[r][c4*4+3] = v.w;
            }
            int c = tid & 63, kk = tid >> 6;
            #pragma unroll 8
            for (int kq = 0; kq < 32; kq++) {
                int k = kq * 4 + kk;
                KsT[c][k] = g_kpe[((size_t)b * KV + k0 + k) * DR + c];
            }
        }
        __syncthreads();
        #pragma unroll 8
        for (int cc = 0; cc < 64; cc++) {
            unsigned long long kA = *(const unsigned long long*)&KsT[cc][lane * 2];
            unsigned long long kB = *(const unsigned long long*)&KsT[cc][lane * 2 + 64];
            #pragma unroll
            for (int i = 0; i < 4; i++) {
                float q = Qs[wid + 8 * i][cc];
                unsigned long long qq = pack2(q, q);
                ffma2(acc[i][0], qq, kA);
                ffma2(acc[i][1], qq, kB);
            }
        }
        __syncthreads();
    }
    const float sc = rsqrtf((float)DQ);
    #pragma unroll
    for (int i = 0; i < 4; i++) {
        #pragma unroll
        for (int jj = 0; jj < 2; jj++) {
            float lo, hi; unpack2(acc[i][jj], lo, hi);
            float2 v = make_float2(lo * sc, hi * sc);
            *(float2*)&g_scores[(size_t)(b * NH + h0 + wid + 8 * i) * KV + k0 + lane * 2 + 64 * jj] = v;
        }
    }
}

// ---------------- 7) softmax over k ----------------
__global__ void __launch_bounds__(256) softmax_kernel(int KV) {
    int bh = blockIdx.x;
    float* s = g_scores + (size_t)bh * KV;
    int tid = threadIdx.x;  // 256
    int n = KV >> 8;        // per-thread count (8 for KV=2048)
    float v[8];
    float m = -1e30f;
    for (int i = 0; i < n; i++) { v[i] = s[tid + i * 256]; m = fmaxf(m, v[i]); }
    __shared__ float red[256];
    red[tid] = m; __syncthreads();
    for (int st = 128; st; st >>= 1) { if (tid < st) red[tid] = fmaxf(red[tid], red[tid + st]); __syncthreads(); }
    m = red[0]; __syncthreads();
    float sum = 0.f;
    for (int i = 0; i < n; i++) { v[i] = __expf(v[i] - m); sum += v[i]; }
    red[tid] = sum; __syncthreads();
    for (int st = 128; st; st >>= 1) { if (tid < st) red[tid] += red[tid + st]; __syncthreads(); }
    float inv = 1.f / red[0];
    for (int i = 0; i < n; i++) s[tid + i * 256] = v[i] * inv;
}

// ---------------- 8) partial attn·c_kv (split-K = 4), FFMA2-packed ----------------
// block tile: 32 heads x 128 c over KV/4 keys.  grid (4, 4, B*4)
__global__ void __launch_bounds__(256) actv_kernel(const float* __restrict__ ckv, int KV) {
    __shared__ float As[32][68];
    __shared__ float Bs[64][128];
    int c0 = blockIdx.x * 128, h0 = blockIdx.y * 32;
    int b = blockIdx.z >> 2, sp = blockIdx.z & 3;
    int kbeg = sp * (KV / 4);
    int tid = threadIdx.x, lane = tid & 31, wid = tid >> 5;
    unsigned long long acc[4][2] = {};  // 4 heads x 4 c (2x float2)
    for (int kc0 = kbeg; kc0 < kbeg + KV / 4; kc0 += 64) {
        #pragma unroll
        for (int t = tid; t < 32 * 16; t += 256) {
            int r = t >> 4, c4 = t & 15;
            float4 v = *(const float4*)&g_scores[(size_t)(b * NH + h0 + r) * KV + kc0 + c4 * 4];
            *(float4*)&As[r][c4 * 4] = v;
        }
        #pragma unroll
        for (int t = tid; t < 64 * 32; t += 256) {
            int r = t >> 5, c4 = t & 31;
            *(float4*)&Bs[r][c4 * 4] =
                *(const float4*)&ckv[((size_t)b * KV + kc0 + r) * KVLR + c0 + c4 * 4];
        }
        __syncthreads();
        #pragma unroll 8
        for (int kc = 0; kc < 64; kc++) {
            unsigned long long b0 = *(const unsigned long long*)&Bs[kc][lane * 4];
            unsigned long long b1 = *(const unsigned long long*)&Bs[kc][lane * 4 + 2];
            #pragma unroll
            for (int i = 0; i < 4; i++) {
                float a = As[wid + 8 * i][kc];
                unsigned long long aa = pack2(a, a);
                ffma2(acc[i][0], aa, b0);
                ffma2(acc[i][1], aa, b1);
            }
        }
        __syncthreads();
    }
    #pragma unroll
    for (int i = 0; i < 4; i++) {
        float x0, x1, x2, x3;
        unpack2(acc[i][0], x0, x1);
        unpack2(acc[i][1], x2, x3);
        float4 v = make_float4(x0, x1, x2, x3);
        *(float4*)&g_part[sp][(size_t)(b * NH + h0 + wid + 8 * i) * KVLR + c0 + lane * 4] = v;
    }
}

// ---------------- 9) out_v[b,h,dv] = sum_c (attn·c_kv)[b,h,c] * W_v[h,dv,c] ----------------
__global__ void __launch_bounds__(256) outv_kernel(const float* __restrict__ kvb) {
    int h = blockIdx.x;               // 128 blocks
    __shared__ float as[2 * KVLR];    // [b][c]
    int tid = threadIdx.x;            // 256
    for (int t = tid; t < 2 * KVLR; t += 256) {
        int b = t >> 9, c = t & 511;
        float v = 0.f;
        #pragma unroll
        for (int sp = 0; sp < 4; sp++) v += g_part[sp][(size_t)(b * NH + h) * KVLR + c];
        as[t] = v;
    }
    __syncthreads();
    int lane = tid & 31, wid = tid >> 5;
    #pragma unroll 2
    for (int r = 0; r < 16; r++) {
        int dv = wid * 16 + r;
        const float4* wp = (const float4*)(kvb + (size_t)(h * 256 + 128 + dv) * KVLR);
        float a0 = 0.f, a1 = 0.f;
        #pragma unroll 4
        for (int c4 = lane; c4 < KVLR / 4; c4 += 32) {
            float4 w = wp[c4];
            int c = c4 * 4;
            a0 += w.x * as[c] + w.y * as[c + 1] + w.z * as[c + 2] + w.w * as[c + 3];
            a1 += w.x * as[512 + c] + w.y * as[512 + c + 1] + w.z * as[512 + c + 2] + w.w * as[512 + c + 3];
        }
        a0 = warp_sum(a0); a1 = warp_sum(a1);
        if (!lane) {
            g_outv[h * DV + dv] = a0;
            g_outv[NH * DV + h * DV + dv] = a1;
        }
    }
}

// ---------------- 10) final = out_v @ o_w^T ----------------
__global__ void __launch_bounds__(256) oproj_kernel(const float* __restrict__ ow, float* __restrict__ out) {
    int row  = blockIdx.x * 8 + (threadIdx.x >> 5);
    int lane = threadIdx.x & 31;
    const float4* wr = (const float4*)(ow + (size_t)row * (NH * DV));
    const float4* x0 = (const float4*)g_outv;
    const float4* x1 = (const float4*)(g_outv + NH * DV);
    float a0 = 0.f, a1 = 0.f;
    #pragma unroll 8
    for (int c = lane; c < (NH * DV) / 4; c += 32) {
        float4 wv = __ldcs(&wr[c]);
        float4 v0 = x0[c], v1 = x1[c];
        a0 += wv.x * v0.x + wv.y * v0.y + wv.z * v0.z + wv.w * v0.w;
        a1 += wv.x * v1.x + wv.y * v1.y + wv.z * v1.z + wv.w * v1.w;
    }
    a0 = warp_sum(a0); a1 = warp_sum(a1);
    if (!lane) { out[row] = a0; out[H + row] = a1; }
}

// ---------------- launch ----------------
extern "C" void kernel_launch(void* const* d_in, const int* in_sizes, int n_in,
                              void* d_out, int out_size) {
    const float* hidden = (const float*)d_in[0];
    const float* ckv    = (const float*)d_in[1];
    const float* kpe    = (const float*)d_in[2];
    const float* qaw    = (const float*)d_in[3];
    const float* lnw    = (const float*)d_in[4];
    const float* qbw    = (const float*)d_in[5];
    const float* kvb    = (const float*)d_in[6];
    const float* ow     = (const float*)d_in[7];
    float* out = (float*)d_out;

    int B  = in_sizes[0] / H;          // 2
    int KV = in_sizes[2] / (B * DR);   // 2048

    qa_gemv<<<QLR, 128>>>(hidden, qaw);
    rmsnorm_k<<<B, 512>>>(lnw);
    qb_gemv<<<(NH * DQ) / 8, 256>>>(qbw);
    rope_all<<<(B * KV * 32 + B * NH * 32 + 255) / 256, 256>>>(kpe, KV);
    qabs_kernel<<<NH, 512>>>(kvb);
    scores_kernel<<<dim3(KV / 128, NH / 32, B), 256>>>(ckv, KV);
    softmax_kernel<<<B * NH, 256>>>(KV);
    actv_kernel<<<dim3(KVLR / 128, NH / 32, B * 4), 256>>>(ckv, KV);
    outv_kernel<<<NH, 256>>>(kvb);
    oproj_kernel<<<H / 8, 256>>>(ow, out);
}

// round 4
// speedup vs baseline: 1.1804x; 1.0126x over previous
#include <cuda_runtime.h>
#include <math.h>

#define H    5120
#define NH   128
#define QLR  1536
#define DR   64
#define KVLR 512
#define DV   128
#define DN   128
#define DQ   192
#define BMAX 2
#define KVMAX 2048

// ---------------- scratch (device globals; no allocation allowed) ----------------
__device__ float g_qa[BMAX * QLR];
__device__ float g_q[BMAX * NH * DQ];
__device__ float g_qpe[BMAX * NH * DR];
__device__ float g_qabs[BMAX * NH * KVLR];
__device__ float g_kpe[BMAX * KVMAX * DR];
__device__ float g_scores[BMAX * NH * KVMAX];
__device__ float g_part[4][BMAX * NH * KVLR];
__device__ float g_outv[BMAX * NH * DV];

__device__ __forceinline__ float warp_sum(float v) {
    #pragma unroll
    for (int o = 16; o; o >>= 1) v += __shfl_xor_sync(0xFFFFFFFFu, v, o);
    return v;
}

// ---- packed fp32x2 helpers (sm_100+; SASS FFMA2 -> 2x fp32 MAC rate, bit-exact) ----
__device__ __forceinline__ unsigned long long pack2(float lo, float hi) {
    unsigned long long r;
    asm("mov.b64 %0, {%1, %2};" : "=l"(r) : "f"(lo), "f"(hi));
    return r;
}
__device__ __forceinline__ void unpack2(unsigned long long v, float& lo, float& hi) {
    asm("mov.b64 {%0, %1}, %2;" : "=f"(lo), "=f"(hi) : "l"(v));
}
__device__ __forceinline__ void ffma2(unsigned long long& d, unsigned long long a, unsigned long long b) {
    asm("fma.rn.f32x2 %0, %1, %2, %0;" : "+l"(d) : "l"(a), "l"(b));
}

// ---------------- 1) q_a = hidden @ q_a_w^T (block per row, both batches) ----------------
__global__ void __launch_bounds__(128) qa_gemv(const float* __restrict__ hs, const float* __restrict__ w) {
    int row = blockIdx.x;
    int tid = threadIdx.x;  // 128
    const float4* wr = (const float4*)(w + (size_t)row * H);
    const float4* x0 = (const float4*)hs;
    const float4* x1 = (const float4*)(hs + H);
    float a0 = 0.f, a1 = 0.f;
    #pragma unroll 10
    for (int c = tid; c < H / 4; c += 128) {
        float4 wv = __ldcs(&wr[c]);
        float4 v0 = x0[c], v1 = x1[c];
        a0 += wv.x * v0.x + wv.y * v0.y + wv.z * v0.z + wv.w * v0.w;
        a1 += wv.x * v1.x + wv.y * v1.y + wv.z * v1.z + wv.w * v1.w;
    }
    a0 = warp_sum(a0); a1 = warp_sum(a1);
    __shared__ float r0[4], r1[4];
    int lane = tid & 31, wid = tid >> 5;
    if (!lane) { r0[wid] = a0; r1[wid] = a1; }
    __syncthreads();
    if (tid == 0) g_qa[row]       = r0[0] + r0[1] + r0[2] + r0[3];
    if (tid == 1) g_qa[QLR + row] = r1[0] + r1[1] + r1[2] + r1[3];
}

// ---------------- 2) RMSNorm(q_a) in place ----------------
__global__ void __launch_bounds__(512) rmsnorm_k(const float* __restrict__ lnw) {
    int b = blockIdx.x, tid = threadIdx.x;  // 512 threads
    float x[3]; float ss = 0.f;
    #pragma unroll
    for (int i = 0; i < 3; i++) { x[i] = g_qa[b * QLR + tid + i * 512]; ss += x[i] * x[i]; }
    __shared__ float red[512];
    red[tid] = ss; __syncthreads();
    for (int s = 256; s; s >>= 1) { if (tid < s) red[tid] += red[tid + s]; __syncthreads(); }
    float inv = rsqrtf(red[0] / (float)QLR + 1e-6f);
    #pragma unroll
    for (int i = 0; i < 3; i++)
        g_qa[b * QLR + tid + i * 512] = x[i] * inv * lnw[tid + i * 512];
}

// ---------------- 3) q = q_a @ q_b_w^T (2 rows per warp: 2 loads/row/iter) ----------------
__global__ void __launch_bounds__(128) qb_gemv(const float* __restrict__ w) {
    int wid  = threadIdx.x >> 5;
    int lane = threadIdx.x & 31;
    int r0 = blockIdx.x * 8 + wid * 2;           // rows r0, r0+1
    const float4* w0 = (const float4*)(w + (size_t)r0 * QLR);
    const float4* w1 = (const float4*)(w + (size_t)(r0 + 1) * QLR);
    const float4* x0 = (const float4*)g_qa;
    const float4* x1 = (const float4*)(g_qa + QLR);
    float a00 = 0.f, a01 = 0.f, a10 = 0.f, a11 = 0.f;
    #pragma unroll 6
    for (int c = lane; c < QLR / 4; c += 32) {
        float4 wa = __ldcs(&w0[c]);
        float4 wb = __ldcs(&w1[c]);
        float4 v0 = x0[c], v1 = x1[c];
        a00 += wa.x * v0.x + wa.y * v0.y + wa.z * v0.z + wa.w * v0.w;
        a01 += wa.x * v1.x + wa.y * v1.y + wa.z * v1.z + wa.w * v1.w;
        a10 += wb.x * v0.x + wb.y * v0.y + wb.z * v0.z + wb.w * v0.w;
        a11 += wb.x * v1.x + wb.y * v1.y + wb.z * v1.z + wb.w * v1.w;
    }
    a00 = warp_sum(a00); a01 = warp_sum(a01);
    a10 = warp_sum(a10); a11 = warp_sum(a11);
    if (!lane) {
        g_q[r0] = a00;           g_q[NH * DQ + r0] = a01;
        g_q[r0 + 1] = a10;       g_q[NH * DQ + r0 + 1] = a11;
    }
}

// ---------------- 4) RoPE on k_pe cache AND q_pe (fast sincos, one kernel) ----------------
#define LOG2_THETA 13.287712379549449f
__global__ void __launch_bounds__(256) rope_all(const float* __restrict__ kpe, int KV) {
    int idx = blockIdx.x * 256 + threadIdx.x;  // pair index
    int nk = 2 * KV * 32;
    if (idx < nk) {
        int i = idx & 31;
        int k = (idx >> 5) % KV;
        int b = idx / (KV * 32);
        float ifr = exp2f(-LOG2_THETA * (float)(2 * i) / 64.0f);
        float s, c; __sincosf((float)k * ifr, &s, &c);
        size_t base = ((size_t)b * KV + k) * DR + 2 * i;
        float x0 = kpe[base], x1 = kpe[base + 1];
        g_kpe[base]     = x0 * c - x1 * s;
        g_kpe[base + 1] = x0 * s + x1 * c;
    } else {
        idx -= nk;
        if (idx >= 2 * NH * 32) return;
        int i = idx & 31;
        int h = (idx >> 5) % NH;
        int b = idx / (NH * 32);
        float ifr = exp2f(-LOG2_THETA * (float)(2 * i) / 64.0f);
        float s, c; __sincosf((float)(KV - 1) * ifr, &s, &c);
        float x0 = g_q[b * NH * DQ + h * DQ + DN + 2 * i];
        float x1 = g_q[b * NH * DQ + h * DQ + DN + 2 * i + 1];
        g_qpe[(b * NH + h) * DR + 2 * i]     = x0 * c - x1 * s;
        g_qpe[(b * NH + h) * DR + 2 * i + 1] = x0 * s + x1 * c;
    }
}

// ---------------- 5) q_abs[b,h,c] = sum_d q_nope[b,h,d] * kv_b_w[h*256+d, c] ----------------
__global__ void __launch_bounds__(512) qabs_kernel(const float* __restrict__ kvb) {
    int h = blockIdx.x;          // 128 blocks
    int c = threadIdx.x;         // 512 threads
    __shared__ float qn[2][DN];
    if (c < 256) qn[c >> 7][c & 127] = g_q[(c >> 7) * NH * DQ + h * DQ + (c & 127)];
    __syncthreads();
    const float* wp = kvb + (size_t)(h * 256) * KVLR + c;
    float a0 = 0.f, a1 = 0.f;
    #pragma unroll 16
    for (int d = 0; d < DN; d++) {
        float w = __ldcs(&wp[(size_t)d * KVLR]);
        a0 += qn[0][d] * w;
        a1 += qn[1][d] * w;
    }
    g_qabs[h * KVLR + c] = a0;
    g_qabs[NH * KVLR + h * KVLR + c] = a1;
}

// ---------------- 6) scores[b,h,k] = (q_abs·c_kv + q_pe·k_pe) * scale ----------------
// block tile: 32 heads x 128 k.  grid (KV/128, 4, B).  FFMA2-packed inner loop.
__global__ void __launch_bounds__(256) scores_kernel(const float* __restrict__ ckv, int KV) {
    __shared__ float Qs[32][66];     // [h-local][channel in chunk]
    __shared__ float KsT[64][130];   // [channel in chunk][k-local], pad 2 (even -> float2 aligned)
    int b = blockIdx.z, h0 = blockIdx.y * 32, k0 = blockIdx.x * 128;
    int tid = threadIdx.x, lane = tid & 31, wid = tid >> 5;
    // thread owns h = h0 + wid + 8i (i=0..3), k = k0 + lane*2 + 64*jj + {0,1} (jj=0..1)
    unsigned long long acc[4][2] = {};
    for (int chunk = 0; chunk < 9; chunk++) {
        if (chunk < 8) {
            int c0 = chunk * 64;
            #pragma unroll
            for (int t = tid; t < 32 * 16; t += 256) {
                int r = t >> 4, c4 = t & 15;
                float4 v = *(const float4*)&g_qabs[((b * NH) + h0 + r) * KVLR + c0 + c4 * 4];
                Qs[r][c4*4+0] = v.x; Qs[r][c4*4+1] = v.y; Qs[r][c4*4+2] = v.z; Qs[r][c4*4+3] = v.w;
            }
            int c = tid & 63, kk = tid >> 6;
            #pragma unroll 8
            for (int kq = 0; kq < 32; kq++) {
                int k = kq * 4 + kk;
                KsT[c][k] = ckv[((size_t)b * KV + k0 + k) * KVLR + c0 + c];
            }
        } else {
            #pragma unroll
            for (int t = tid; t < 32 * 16; t += 256) {
                int r = t >> 4, c4 = t & 15;
                float4 v = *(const float4*)&g_qpe[((b * NH) + h0 + r) * DR + c4 * 4];
                Qs[r][c4*4+0] = v.x; Qs[r][c4*4+1] = v.y; Qs[r][c4*4+2] = v.z; Qs[r][c4*4+3] = v.w;
            }
            int c = tid & 63, kk = tid >> 6;
            #pragma unroll 8
            for (int kq = 0; kq < 32; kq++) {
                int k = kq * 4 + kk;
                KsT[c][k] = g_kpe[((size_t)b * KV + k0 + k) * DR + c];
            }
        }
        __syncthreads();
        #pragma unroll 8
        for (int cc = 0; cc < 64; cc++) {
            unsigned long long kA = *(const unsigned long long*)&KsT[cc][lane * 2];
            unsigned long long kB = *(const unsigned long long*)&KsT[cc][lane * 2 + 64];
            #pragma unroll
            for (int i = 0; i < 4; i++) {
                float q = Qs[wid + 8 * i][cc];
                unsigned long long qq = pack2(q, q);
                ffma2(acc[i][0], qq, kA);
                ffma2(acc[i][1], qq, kB);
            }
        }
        __syncthreads();
    }
    const float sc = rsqrtf((float)DQ);
    #pragma unroll
    for (int i = 0; i < 4; i++) {
        #pragma unroll
        for (int jj = 0; jj < 2; jj++) {
            float lo, hi; unpack2(acc[i][jj], lo, hi);
            float2 v = make_float2(lo * sc, hi * sc);
            *(float2*)&g_scores[(size_t)(b * NH + h0 + wid + 8 * i) * KV + k0 + lane * 2 + 64 * jj] = v;
        }
    }
}

// ---------------- 7) softmax over k ----------------
__global__ void __launch_bounds__(256) softmax_kernel(int KV) {
    int bh = blockIdx.x;
    float* s = g_scores + (size_t)bh * KV;
    int tid = threadIdx.x;  // 256
    int n = KV >> 8;        // per-thread count (8 for KV=2048)
    float v[8];
    float m = -1e30f;
    for (int i = 0; i < n; i++) { v[i] = s[tid + i * 256]; m = fmaxf(m, v[i]); }
    __shared__ float red[256];
    red[tid] = m; __syncthreads();
    for (int st = 128; st; st >>= 1) { if (tid < st) red[tid] = fmaxf(red[tid], red[tid + st]); __syncthreads(); }
    m = red[0]; __syncthreads();
    float sum = 0.f;
    for (int i = 0; i < n; i++) { v[i] = __expf(v[i] - m); sum += v[i]; }
    red[tid] = sum; __syncthreads();
    for (int st = 128; st; st >>= 1) { if (tid < st) red[tid] += red[tid + st]; __syncthreads(); }
    float inv = 1.f / red[0];
    for (int i = 0; i < n; i++) s[tid + i * 256] = v[i] * inv;
}

// ---------------- 8) partial attn·c_kv (split-K = 4), FFMA2-packed ----------------
// block tile: 32 heads x 128 c over KV/4 keys.  grid (4, 4, B*4)
__global__ void __launch_bounds__(256) actv_kernel(const float* __restrict__ ckv, int KV) {
    __shared__ float As[32][68];
    __shared__ float Bs[64][128];
    int c0 = blockIdx.x * 128, h0 = blockIdx.y * 32;
    int b = blockIdx.z >> 2, sp = blockIdx.z & 3;
    int kbeg = sp * (KV / 4);
    int tid = threadIdx.x, lane = tid & 31, wid = tid >> 5;
    unsigned long long acc[4][2] = {};  // 4 heads x 4 c (2x float2)
    for (int kc0 = kbeg; kc0 < kbeg + KV / 4; kc0 += 64) {
        #pragma unroll
        for (int t = tid; t < 32 * 16; t += 256) {
            int r = t >> 4, c4 = t & 15;
            float4 v = *(const float4*)&g_scores[(size_t)(b * NH + h0 + r) * KV + kc0 + c4 * 4];
            *(float4*)&As[r][c4 * 4] = v;
        }
        #pragma unroll
        for (int t = tid; t < 64 * 32; t += 256) {
            int r = t >> 5, c4 = t & 31;
            *(float4*)&Bs[r][c4 * 4] =
                *(const float4*)&ckv[((size_t)b * KV + kc0 + r) * KVLR + c0 + c4 * 4];
        }
        __syncthreads();
        #pragma unroll 8
        for (int kc = 0; kc < 64; kc++) {
            unsigned long long b0 = *(const unsigned long long*)&Bs[kc][lane * 4];
            unsigned long long b1 = *(const unsigned long long*)&Bs[kc][lane * 4 + 2];
            #pragma unroll
            for (int i = 0; i < 4; i++) {
                float a = As[wid + 8 * i][kc];
                unsigned long long aa = pack2(a, a);
                ffma2(acc[i][0], aa, b0);
                ffma2(acc[i][1], aa, b1);
            }
        }
        __syncthreads();
    }
    #pragma unroll
    for (int i = 0; i < 4; i++) {
        float x0, x1, x2, x3;
        unpack2(acc[i][0], x0, x1);
        unpack2(acc[i][1], x2, x3);
        float4 v = make_float4(x0, x1, x2, x3);
        *(float4*)&g_part[sp][(size_t)(b * NH + h0 + wid + 8 * i) * KVLR + c0 + lane * 4] = v;
    }
}

// ---------------- 9) out_v[b,h,dv] = sum_c (attn·c_kv)[b,h,c] * W_v[h,dv,c] ----------------
__global__ void __launch_bounds__(256) outv_kernel(const float* __restrict__ kvb) {
    int h = blockIdx.x;               // 128 blocks
    __shared__ float as[2 * KVLR];    // [b][c]
    int tid = threadIdx.x;            // 256
    for (int t = tid; t < 2 * KVLR; t += 256) {
        int b = t >> 9, c = t & 511;
        float v = 0.f;
        #pragma unroll
        for (int sp = 0; sp < 4; sp++) v += g_part[sp][(size_t)(b * NH + h) * KVLR + c];
        as[t] = v;
    }
    __syncthreads();
    int lane = tid & 31, wid = tid >> 5;
    #pragma unroll 2
    for (int r = 0; r < 16; r++) {
        int dv = wid * 16 + r;
        const float4* wp = (const float4*)(kvb + (size_t)(h * 256 + 128 + dv) * KVLR);
        float a0 = 0.f, a1 = 0.f;
        #pragma unroll 4
        for (int c4 = lane; c4 < KVLR / 4; c4 += 32) {
            float4 w = __ldcs(&wp[c4]);
            int c = c4 * 4;
            a0 += w.x * as[c] + w.y * as[c + 1] + w.z * as[c + 2] + w.w * as[c + 3];
            a1 += w.x * as[512 + c] + w.y * as[512 + c + 1] + w.z * as[512 + c + 2] + w.w * as[512 + c + 3];
        }
        a0 = warp_sum(a0); a1 = warp_sum(a1);
        if (!lane) {
            g_outv[h * DV + dv] = a0;
            g_outv[NH * DV + h * DV + dv] = a1;
        }
    }
}

// ---------------- 10) final = out_v @ o_w^T (2 rows per warp: 2 loads/row/iter) ----------------
__global__ void __launch_bounds__(128) oproj_kernel(const float* __restrict__ ow, float* __restrict__ out) {
    int wid  = threadIdx.x >> 5;
    int lane = threadIdx.x & 31;
    int r0 = blockIdx.x * 8 + wid * 2;          // rows r0, r0+1
    const float4* w0 = (const float4*)(ow + (size_t)r0 * (NH * DV));
    const float4* w1 = (const float4*)(ow + (size_t)(r0 + 1) * (NH * DV));
    const float4* x0 = (const float4*)g_outv;
    const float4* x1 = (const float4*)(g_outv + NH * DV);
    float a00 = 0.f, a01 = 0.f, a10 = 0.f, a11 = 0.f;
    #pragma unroll 8
    for (int c = lane; c < (NH * DV) / 4; c += 32) {
        float4 wa = __ldcs(&w0[c]);
        float4 wb = __ldcs(&w1[c]);
        float4 v0 = x0[c], v1 = x1[c];
        a00 += wa.x * v0.x + wa.y * v0.y + wa.z * v0.z + wa.w * v0.w;
        a01 += wa.x * v1.x + wa.y * v1.y + wa.z * v1.z + wa.w * v1.w;
        a10 += wb.x * v0.x + wb.y * v0.y + wb.z * v0.z + wb.w * v0.w;
        a11 += wb.x * v1.x + wb.y * v1.y + wb.z * v1.z + wb.w * v1.w;
    }
    a00 = warp_sum(a00); a01 = warp_sum(a01);
    a10 = warp_sum(a10); a11 = warp_sum(a11);
    if (!lane) {
        out[r0] = a00;       out[H + r0] = a01;
        out[r0 + 1] = a10;   out[H + r0 + 1] = a11;
    }
}

// ---------------- launch ----------------
extern "C" void kernel_launch(void* const* d_in, const int* in_sizes, int n_in,
                              void* d_out, int out_size) {
    const float* hidden = (const float*)d_in[0];
    const float* ckv    = (const float*)d_in[1];
    const float* kpe    = (const float*)d_in[2];
    const float* qaw    = (const float*)d_in[3];
    const float* lnw    = (const float*)d_in[4];
    const float* qbw    = (const float*)d_in[5];
    const float* kvb    = (const float*)d_in[6];
    const float* ow     = (const float*)d_in[7];
    float* out = (float*)d_out;

    int B  = in_sizes[0] / H;          // 2
    int KV = in_sizes[2] / (B * DR);   // 2048

    qa_gemv<<<QLR, 128>>>(hidden, qaw);
    rmsnorm_k<<<B, 512>>>(lnw);
    qb_gemv<<<(NH * DQ) / 8, 128>>>(qbw);
    rope_all<<<(B * KV * 32 + B * NH * 32 + 255) / 256, 256>>>(kpe, KV);
    qabs_kernel<<<NH, 512>>>(kvb);
    scores_kernel<<<dim3(KV / 128, NH / 32, B), 256>>>(ckv, KV);
    softmax_kernel<<<B * NH, 256>>>(KV);
    actv_kernel<<<dim3(KVLR / 128, NH / 32, B * 4), 256>>>(ckv, KV);
    outv_kernel<<<NH, 256>>>(kvb);
    oproj_kernel<<<H / 8, 128>>>(ow, out);
}

// round 6
// speedup vs baseline: 1.2435x; 1.0534x over previous
#include <cuda_runtime.h>
#include <math.h>

#define H    5120
#define NH   128
#define QLR  1536
#define DR   64
#define KVLR 512
#define DV   128
#define DN   128
#define DQ   192
#define BMAX 2
#define KVMAX 2048

// ---------------- scratch (device globals; no allocation allowed) ----------------
__device__ float g_qa[BMAX * QLR];
__device__ float g_q[BMAX * NH * DQ];
__device__ float g_qpe[BMAX * NH * DR];
__device__ float g_qabs[BMAX * NH * KVLR];
__device__ float g_kpe[BMAX * KVMAX * DR];
__device__ float g_scores[BMAX * NH * KVMAX];
__device__ float g_part[4][BMAX * NH * KVLR];
__device__ float g_outv[BMAX * NH * DV];

__device__ __forceinline__ float warp_sum(float v) {
    #pragma unroll
    for (int o = 16; o; o >>= 1) v += __shfl_xor_sync(0xFFFFFFFFu, v, o);
    return v;
}

// ---- packed fp32x2 helpers (sm_100+; SASS FFMA2 -> 2x fp32 MAC rate, bit-exact) ----
__device__ __forceinline__ unsigned long long pack2(float lo, float hi) {
    unsigned long long r;
    asm("mov.b64 %0, {%1, %2};" : "=l"(r) : "f"(lo), "f"(hi));
    return r;
}
__device__ __forceinline__ void unpack2(unsigned long long v, float& lo, float& hi) {
    asm("mov.b64 {%0, %1}, %2;" : "=f"(lo), "=f"(hi) : "l"(v));
}
__device__ __forceinline__ void ffma2(unsigned long long& d, unsigned long long a, unsigned long long b) {
    asm("fma.rn.f32x2 %0, %1, %2, %0;" : "+l"(d) : "l"(a), "l"(b));
}

// ---------------- RoPE on k_pe cache (independent; launched FIRST) ----------------
#define LOG2_THETA 13.287712379549449f
__global__ void __launch_bounds__(256) rope_k_kernel(const float* __restrict__ kpe, int KV) {
    int idx = blockIdx.x * 256 + threadIdx.x;  // pair index
    if (idx >= 2 * KV * 32) return;
    int i = idx & 31;
    int k = (idx >> 5) % KV;
    int b = idx / (KV * 32);
    float ifr = exp2f(-LOG2_THETA * (float)(2 * i) / 64.0f);
    float s, c; __sincosf((float)k * ifr, &s, &c);
    size_t base = ((size_t)b * KV + k) * DR + 2 * i;
    float x0 = kpe[base], x1 = kpe[base + 1];
    g_kpe[base]     = x0 * c - x1 * s;
    g_kpe[base + 1] = x0 * s + x1 * c;
}

// ---------------- q_a = hidden @ q_a_w^T (block per row, both batches) ----------------
__global__ void __launch_bounds__(128) qa_gemv(const float* __restrict__ hs, const float* __restrict__ w) {
    int row = blockIdx.x;
    int tid = threadIdx.x;  // 128
    const float4* wr = (const float4*)(w + (size_t)row * H);
    const float4* x0 = (const float4*)hs;
    const float4* x1 = (const float4*)(hs + H);
    float a0 = 0.f, a1 = 0.f;
    #pragma unroll 10
    for (int c = tid; c < H / 4; c += 128) {
        float4 wv = __ldcs(&wr[c]);
        float4 v0 = x0[c], v1 = x1[c];
        a0 += wv.x * v0.x + wv.y * v0.y + wv.z * v0.z + wv.w * v0.w;
        a1 += wv.x * v1.x + wv.y * v1.y + wv.z * v1.z + wv.w * v1.w;
    }
    a0 = warp_sum(a0); a1 = warp_sum(a1);
    __shared__ float r0[4], r1[4];
    int lane = tid & 31, wid = tid >> 5;
    if (!lane) { r0[wid] = a0; r1[wid] = a1; }
    __syncthreads();
    if (tid == 0) g_qa[row]       = r0[0] + r0[1] + r0[2] + r0[3];
    if (tid == 1) g_qa[QLR + row] = r1[0] + r1[1] + r1[2] + r1[3];
}

// ---------------- RMSNorm(q_a) in place ----------------
__global__ void __launch_bounds__(512) rmsnorm_k(const float* __restrict__ lnw) {
    int b = blockIdx.x, tid = threadIdx.x;  // 512 threads
    float x[3]; float ss = 0.f;
    #pragma unroll
    for (int i = 0; i < 3; i++) { x[i] = g_qa[b * QLR + tid + i * 512]; ss += x[i] * x[i]; }
    __shared__ float red[512];
    red[tid] = ss; __syncthreads();
    for (int s = 256; s; s >>= 1) { if (tid < s) red[tid] += red[tid + s]; __syncthreads(); }
    float inv = rsqrtf(red[0] / (float)QLR + 1e-6f);
    #pragma unroll
    for (int i = 0; i < 3; i++)
        g_qa[b * QLR + tid + i * 512] = x[i] * inv * lnw[tid + i * 512];
}

// ---------------- q = q_a @ q_b_w^T (2 rows per warp) -- sits in the ncu -s 5 slot ----------------
__global__ void __launch_bounds__(128) qb_gemv(const float* __restrict__ w) {
    int wid  = threadIdx.x >> 5;
    int lane = threadIdx.x & 31;
    int r0 = blockIdx.x * 8 + wid * 2;           // rows r0, r0+1
    const float4* w0 = (const float4*)(w + (size_t)r0 * QLR);
    const float4* w1 = (const float4*)(w + (size_t)(r0 + 1) * QLR);
    const float4* x0 = (const float4*)g_qa;
    const float4* x1 = (const float4*)(g_qa + QLR);
    float a00 = 0.f, a01 = 0.f, a10 = 0.f, a11 = 0.f;
    #pragma unroll 6
    for (int c = lane; c < QLR / 4; c += 32) {
        float4 wa = __ldcs(&w0[c]);
        float4 wb = __ldcs(&w1[c]);
        float4 v0 = x0[c], v1 = x1[c];
        a00 += wa.x * v0.x + wa.y * v0.y + wa.z * v0.z + wa.w * v0.w;
        a01 += wa.x * v1.x + wa.y * v1.y + wa.z * v1.z + wa.w * v1.w;
        a10 += wb.x * v0.x + wb.y * v0.y + wb.z * v0.z + wb.w * v0.w;
        a11 += wb.x * v1.x + wb.y * v1.y + wb.z * v1.z + wb.w * v1.w;
    }
    a00 = warp_sum(a00); a01 = warp_sum(a01);
    a10 = warp_sum(a10); a11 = warp_sum(a11);
    if (!lane) {
        g_q[r0] = a00;           g_q[NH * DQ + r0] = a01;
        g_q[r0 + 1] = a10;       g_q[NH * DQ + r0 + 1] = a11;
    }
}

// ---------------- RoPE on q_pe (position KV-1) ----------------
__global__ void __launch_bounds__(256) rope_q_kernel(int KV) {
    int idx = blockIdx.x * 256 + threadIdx.x;
    if (idx >= 2 * NH * 32) return;
    int i = idx & 31;
    int h = (idx >> 5) % NH;
    int b = idx / (NH * 32);
    float ifr = exp2f(-LOG2_THETA * (float)(2 * i) / 64.0f);
    float s, c; __sincosf((float)(KV - 1) * ifr, &s, &c);
    float x0 = g_q[b * NH * DQ + h * DQ + DN + 2 * i];
    float x1 = g_q[b * NH * DQ + h * DQ + DN + 2 * i + 1];
    g_qpe[(b * NH + h) * DR + 2 * i]     = x0 * c - x1 * s;
    g_qpe[(b * NH + h) * DR + 2 * i + 1] = x0 * s + x1 * c;
}

// ---------------- q_abs[b,h,c] = sum_d q_nope[b,h,d] * kv_b_w[h*256+d, c] ----------------
__global__ void __launch_bounds__(512) qabs_kernel(const float* __restrict__ kvb) {
    int h = blockIdx.x;          // 128 blocks
    int c = threadIdx.x;         // 512 threads
    __shared__ float qn[2][DN];
    if (c < 256) qn[c >> 7][c & 127] = g_q[(c >> 7) * NH * DQ + h * DQ + (c & 127)];
    __syncthreads();
    const float* wp = kvb + (size_t)(h * 256) * KVLR + c;
    float a0 = 0.f, a1 = 0.f;
    #pragma unroll 16
    for (int d = 0; d < DN; d++) {
        float w = __ldcs(&wp[(size_t)d * KVLR]);
        a0 += qn[0][d] * w;
        a1 += qn[1][d] * w;
    }
    g_qabs[h * KVLR + c] = a0;
    g_qabs[NH * KVLR + h * KVLR + c] = a1;
}

// ---------------- scores[b,h,k] = (q_abs·c_kv + q_pe·k_pe) * scale ----------------
// block tile: 32 heads x 128 k.  grid (KV/128, 4, B).  FFMA2-packed inner loop.
__global__ void __launch_bounds__(256) scores_kernel(const float* __restrict__ ckv, int KV) {
    __shared__ float Qs[32][66];
    __shared__ float KsT[64][130];
    int b = blockIdx.z, h0 = blockIdx.y * 32, k0 = blockIdx.x * 128;
    int tid = threadIdx.x, lane = tid & 31, wid = tid >> 5;
    unsigned long long acc[4][2] = {};
    for (int chunk = 0; chunk < 9; chunk++) {
        if (chunk < 8) {
            int c0 = chunk * 64;
            #pragma unroll
            for (int t = tid; t < 32 * 16; t += 256) {
                int r = t >> 4, c4 = t & 15;
                float4 v = *(const float4*)&g_qabs[((b * NH) + h0 + r) * KVLR + c0 + c4 * 4];
                Qs[r][c4*4+0] = v.x; Qs[r][c4*4+1] = v.y; Qs[r][c4*4+2] = v.z; Qs[r][c4*4+3] = v.w;
            }
            int c = tid & 63, kk = tid >> 6;
            #pragma unroll 8
            for (int kq = 0; kq < 32; kq++) {
                int k = kq * 4 + kk;
                KsT[c][k] = ckv[((size_t)b * KV + k0 + k) * KVLR + c0 + c];
            }
        } else {
            #pragma unroll
            for (int t = tid; t < 32 * 16; t += 256) {
                int r = t >> 4, c4 = t & 15;
                float4 v = *(const float4*)&g_qpe[((b * NH) + h0 + r) * DR + c4 * 4];
                Qs[r][c4*4+0] = v.x; Qs[r][c4*4+1] = v.y; Qs[r][c4*4+2] = v.z; Qs[r][c4*4+3] = v.w;
            }
            int c = tid & 63, kk = tid >> 6;
            #pragma unroll 8
            for (int kq = 0; kq < 32; kq++) {
                int k = kq * 4 + kk;
                KsT[c][k] = g_kpe[((size_t)b * KV + k0 + k) * DR + c];
            }
        }
        __syncthreads();
        #pragma unroll 8
        for (int cc = 0; cc < 64; cc++) {
            unsigned long long kA = *(const unsigned long long*)&KsT[cc][lane * 2];
            unsigned long long kB = *(const unsigned long long*)&KsT[cc][lane * 2 + 64];
            #pragma unroll
            for (int i = 0; i < 4; i++) {
                float q = Qs[wid + 8 * i][cc];
                unsigned long long qq = pack2(q, q);
                ffma2(acc[i][0], qq, kA);
                ffma2(acc[i][1], qq, kB);
            }
        }
        __syncthreads();
    }
    const float sc = rsqrtf((float)DQ);
    #pragma unroll
    for (int i = 0; i < 4; i++) {
        #pragma unroll
        for (int jj = 0; jj < 2; jj++) {
            float lo, hi; unpack2(acc[i][jj], lo, hi);
            float2 v = make_float2(lo * sc, hi * sc);
            *(float2*)&g_scores[(size_t)(b * NH + h0 + wid + 8 * i) * KV + k0 + lane * 2 + 64 * jj] = v;
        }
    }
}

// ---------------- softmax over k ----------------
__global__ void __launch_bounds__(256) softmax_kernel(int KV) {
    int bh = blockIdx.x;
    float* s = g_scores + (size_t)bh * KV;
    int tid = threadIdx.x;  // 256
    int n = KV >> 8;
    float v[8];
    float m = -1e30f;
    for (int i = 0; i < n; i++) { v[i] = s[tid + i * 256]; m = fmaxf(m, v[i]); }
    __shared__ float red[256];
    red[tid] = m; __syncthreads();
    for (int st = 128; st; st >>= 1) { if (tid < st) red[tid] = fmaxf(red[tid], red[tid + st]); __syncthreads(); }
    m = red[0]; __syncthreads();
    float sum = 0.f;
    for (int i = 0; i < n; i++) { v[i] = __expf(v[i] - m); sum += v[i]; }
    red[tid] = sum; __syncthreads();
    for (int st = 128; st; st >>= 1) { if (tid < st) red[tid] += red[tid + st]; __syncthreads(); }
    float inv = 1.f / red[0];
    for (int i = 0; i < n; i++) s[tid + i * 256] = v[i] * inv;
}

// ---------------- partial attn·c_kv (split-K = 4), FFMA2-packed ----------------
__global__ void __launch_bounds__(256) actv_kernel(const float* __restrict__ ckv, int KV) {
    __shared__ float As[32][68];
    __shared__ float Bs[64][128];
    int c0 = blockIdx.x * 128, h0 = blockIdx.y * 32;
    int b = blockIdx.z >> 2, sp = blockIdx.z & 3;
    int kbeg = sp * (KV / 4);
    int tid = threadIdx.x, lane = tid & 31, wid = tid >> 5;
    unsigned long long acc[4][2] = {};
    for (int kc0 = kbeg; kc0 < kbeg + KV / 4; kc0 += 64) {
        #pragma unroll
        for (int t = tid; t < 32 * 16; t += 256) {
            int r = t >> 4, c4 = t & 15;
            float4 v = *(const float4*)&g_scores[(size_t)(b * NH + h0 + r) * KV + kc0 + c4 * 4];
            *(float4*)&As[r][c4 * 4] = v;
        }
        #pragma unroll
        for (int t = tid; t < 64 * 32; t += 256) {
            int r = t >> 5, c4 = t & 31;
            *(float4*)&Bs[r][c4 * 4] =
                *(const float4*)&ckv[((size_t)b * KV + kc0 + r) * KVLR + c0 + c4 * 4];
        }
        __syncthreads();
        #pragma unroll 8
        for (int kc = 0; kc < 64; kc++) {
            unsigned long long b0 = *(const unsigned long long*)&Bs[kc][lane * 4];
            unsigned long long b1 = *(const unsigned long long*)&Bs[kc][lane * 4 + 2];
            #pragma unroll
            for (int i = 0; i < 4; i++) {
                float a = As[wid + 8 * i][kc];
                unsigned long long aa = pack2(a, a);
                ffma2(acc[i][0], aa, b0);
                ffma2(acc[i][1], aa, b1);
            }
        }
        __syncthreads();
    }
    #pragma unroll
    for (int i = 0; i < 4; i++) {
        float x0, x1, x2, x3;
        unpack2(acc[i][0], x0, x1);
        unpack2(acc[i][1], x2, x3);
        float4 v = make_float4(x0, x1, x2, x3);
        *(float4*)&g_part[sp][(size_t)(b * NH + h0 + wid + 8 * i) * KVLR + c0 + lane * 4] = v;
    }
}

// ---------------- out_v: grid 512 = (h, dv-quarter), 256 thr, warp = 4 dv rows ----------------
__global__ void __launch_bounds__(256) outv_kernel(const float* __restrict__ kvb) {
    int h = blockIdx.x >> 2, dvq = blockIdx.x & 3;
    __shared__ float as[2][KVLR];
    int tid = threadIdx.x;            // 256
    for (int t = tid; t < 2 * KVLR; t += 256) {
        int b = t >> 9, c = t & 511;
        float v = 0.f;
        #pragma unroll
        for (int sp = 0; sp < 4; sp++) v += g_part[sp][(size_t)(b * NH + h) * KVLR + c];
        as[b][c] = v;
    }
    __syncthreads();
    int lane = tid & 31, wid = tid >> 5;
    int dv0 = dvq * 32 + wid * 4;                 // 4 consecutive dv rows per warp
    const float4* wp0 = (const float4*)(kvb + (size_t)(h * 256 + 128 + dv0 + 0) * KVLR);
    const float4* wp1 = (const float4*)(kvb + (size_t)(h * 256 + 128 + dv0 + 1) * KVLR);
    const float4* wp2 = (const float4*)(kvb + (size_t)(h * 256 + 128 + dv0 + 2) * KVLR);
    const float4* wp3 = (const float4*)(kvb + (size_t)(h * 256 + 128 + dv0 + 3) * KVLR);
    float a0[4] = {0.f, 0.f, 0.f, 0.f};
    float a1[4] = {0.f, 0.f, 0.f, 0.f};
    #pragma unroll
    for (int c4 = lane; c4 < KVLR / 4; c4 += 32) {   // 4 iterations, all 16 LDG in flight
        float4 w0 = __ldcs(&wp0[c4]);
        float4 w1 = __ldcs(&wp1[c4]);
        float4 w2 = __ldcs(&wp2[c4]);
        float4 w3 = __ldcs(&wp3[c4]);
        float4 v0 = *(const float4*)&as[0][c4 * 4];
        float4 v1 = *(const float4*)&as[1][c4 * 4];
        a0[0] += w0.x*v0.x + w0.y*v0.y + w0.z*v0.z + w0.w*v0.w;
        a1[0] += w0.x*v1.x + w0.y*v1.y + w0.z*v1.z + w0.w*v1.w;
        a0[1] += w1.x*v0.x + w1.y*v0.y + w1.z*v0.z + w1.w*v0.w;
        a1[1] += w1.x*v1.x + w1.y*v1.y + w1.z*v1.z + w1.w*v1.w;
        a0[2] += w2.x*v0.x + w2.y*v0.y + w2.z*v0.z + w2.w*v0.w;
        a1[2] += w2.x*v1.x + w2.y*v1.y + w2.z*v1.z + w2.w*v1.w;
        a0[3] += w3.x*v0.x + w3.y*v0.y + w3.z*v0.z + w3.w*v0.w;
        a1[3] += w3.x*v1.x + w3.y*v1.y + w3.z*v1.z + w3.w*v1.w;
    }
    #pragma unroll
    for (int r = 0; r < 4; r++) {
        a0[r] = warp_sum(a0[r]);
        a1[r] = warp_sum(a1[r]);
    }
    if (!lane) {
        #pragma unroll
        for (int r = 0; r < 4; r++) {
            g_outv[h * DV + dv0 + r] = a0[r];
            g_outv[NH * DV + h * DV + dv0 + r] = a1[r];
        }
    }
}

// ---------------- final = out_v @ o_w^T: 1280 blocks, 2 warps per row (c-halves) ----------------
__global__ void __launch_bounds__(256) oproj_kernel(const float* __restrict__ ow, float* __restrict__ out) {
    int wid  = threadIdx.x >> 5;                  // 8 warps
    int lane = threadIdx.x & 31;
    int r    = blockIdx.x * 4 + (wid >> 1);       // 4 rows/block
    int half = wid & 1;                           // c-half
    const int HALF4 = (NH * DV) / 8;              // 2048 float4 per half
    const float4* wr = (const float4*)(ow + (size_t)r * (NH * DV)) + half * HALF4;
    const float4* x0 = (const float4*)g_outv + half * HALF4;
    const float4* x1 = (const float4*)(g_outv + NH * DV) + half * HALF4;
    float a0 = 0.f, a1 = 0.f;
    #pragma unroll 8
    for (int c = lane; c < HALF4; c += 32) {      // 64 iterations
        float4 wv = __ldcs(&wr[c]);
        float4 v0 = x0[c], v1 = x1[c];
        a0 += wv.x * v0.x + wv.y * v0.y + wv.z * v0.z + wv.w * v0.w;
        a1 += wv.x * v1.x + wv.y * v1.y + wv.z * v1.z + wv.w * v1.w;
    }
    a0 = warp_sum(a0); a1 = warp_sum(a1);
    __shared__ float s0[8], s1[8];
    if (!lane) { s0[wid] = a0; s1[wid] = a1; }
    __syncthreads();
    if (threadIdx.x < 4) {
        int w2 = threadIdx.x * 2;
        out[blockIdx.x * 4 + threadIdx.x] = s0[w2] + s0[w2 + 1];
    } else if (threadIdx.x < 8) {
        int rr = threadIdx.x - 4;
        int w2 = rr * 2;
        out[H + blockIdx.x * 4 + rr] = s1[w2] + s1[w2 + 1];
    }
}

// ---------------- launch ----------------
extern "C" void kernel_launch(void* const* d_in, const int* in_sizes, int n_in,
                              void* d_out, int out_size) {
    const float* hidden = (const float*)d_in[0];
    const float* ckv    = (const float*)d_in[1];
    const float* kpe    = (const float*)d_in[2];
    const float* qaw    = (const float*)d_in[3];
    const float* lnw    = (const float*)d_in[4];
    const float* qbw    = (const float*)d_in[5];
    const float* kvb    = (const float*)d_in[6];
    const float* ow     = (const float*)d_in[7];
    float* out = (float*)d_out;

    int B  = in_sizes[0] / H;          // 2
    int KV = in_sizes[2] / (B * DR);   // 2048

    rope_k_kernel<<<(B * KV * 32 + 255) / 256, 256>>>(kpe, KV);   // 1
    qa_gemv<<<QLR, 128>>>(hidden, qaw);                           // 2
    rmsnorm_k<<<B, 512>>>(lnw);                                   // 3
    qb_gemv<<<(NH * DQ) / 8, 128>>>(qbw);                         // 4  <- ncu -s 5 slot
    rope_q_kernel<<<(B * NH * 32 + 255) / 256, 256>>>(KV);        // 5
    qabs_kernel<<<NH, 512>>>(kvb);                                // 6
    scores_kernel<<<dim3(KV / 128, NH / 32, B), 256>>>(ckv, KV);  // 7
    softmax_kernel<<<B * NH, 256>>>(KV);                          // 8
    actv_kernel<<<dim3(KVLR / 128, NH / 32, B * 4), 256>>>(ckv, KV); // 9
    outv_kernel<<<NH * 4, 256>>>(kvb);                            // 10
    oproj_kernel<<<H / 4, 256>>>(ow, out);                        // 11
}

// round 7
// speedup vs baseline: 1.3319x; 1.0711x over previous
#include <cuda_runtime.h>
#include <math.h>

#define H    5120
#define NH   128
#define QLR  1536
#define DR   64
#define KVLR 512
#define DV   128
#define DN   128
#define DQ   192
#define BMAX 2
#define KVMAX 2048

#define NSM        148
#define PBLOCKS    (NSM * 12)        // persistent grid: 12 blocks/SM x 128 thr
#define PWARPS     (PBLOCKS * 4)     // 7104 persistent warps

// ---------------- scratch (device globals; no allocation allowed) ----------------
__device__ float g_qa[BMAX * QLR];
__device__ float g_q[BMAX * NH * DQ];
__device__ float g_qpe[BMAX * NH * DR];
__device__ float g_qabs[BMAX * NH * KVLR];
__device__ float g_kpe[BMAX * KVMAX * DR];
__device__ float g_scores[BMAX * NH * KVMAX];
__device__ float g_part[4][BMAX * NH * KVLR];
__device__ float g_outv[BMAX * NH * DV];
__device__ float g_opart0[H * 16];   // batch 0 o_proj partials
__device__ float g_opart1[H * 16];   // batch 1 o_proj partials

__device__ __forceinline__ float warp_sum(float v) {
    #pragma unroll
    for (int o = 16; o; o >>= 1) v += __shfl_xor_sync(0xFFFFFFFFu, v, o);
    return v;
}

// ---- packed fp32x2 helpers (sm_100+; SASS FFMA2 -> 2x fp32 MAC rate, bit-exact) ----
__device__ __forceinline__ unsigned long long pack2(float lo, float hi) {
    unsigned long long r;
    asm("mov.b64 %0, {%1, %2};" : "=l"(r) : "f"(lo), "f"(hi));
    return r;
}
__device__ __forceinline__ void unpack2(unsigned long long v, float& lo, float& hi) {
    asm("mov.b64 {%0, %1}, %2;" : "=f"(lo), "=f"(hi) : "l"(v));
}
__device__ __forceinline__ void ffma2(unsigned long long& d, unsigned long long a, unsigned long long b) {
    asm("fma.rn.f32x2 %0, %1, %2, %0;" : "+l"(d) : "l"(a), "l"(b));
}

// ---------------- RoPE on k_pe cache (independent; launched FIRST) ----------------
#define LOG2_THETA 13.287712379549449f
__global__ void __launch_bounds__(256) rope_k_kernel(const float* __restrict__ kpe, int KV) {
    int idx = blockIdx.x * 256 + threadIdx.x;  // pair index
    if (idx >= 2 * KV * 32) return;
    int i = idx & 31;
    int k = (idx >> 5) % KV;
    int b = idx / (KV * 32);
    float ifr = exp2f(-LOG2_THETA * (float)(2 * i) / 64.0f);
    float s, c; __sincosf((float)k * ifr, &s, &c);
    size_t base = ((size_t)b * KV + k) * DR + 2 * i;
    float x0 = kpe[base], x1 = kpe[base + 1];
    g_kpe[base]     = x0 * c - x1 * s;
    g_kpe[base + 1] = x0 * s + x1 * c;
}

// ---------------- q_a = hidden @ q_a_w^T (block per row, both batches) ----------------
__global__ void __launch_bounds__(128) qa_gemv(const float* __restrict__ hs, const float* __restrict__ w) {
    int row = blockIdx.x;
    int tid = threadIdx.x;  // 128
    const float4* wr = (const float4*)(w + (size_t)row * H);
    const float4* x0 = (const float4*)hs;
    const float4* x1 = (const float4*)(hs + H);
    float a0 = 0.f, a1 = 0.f;
    #pragma unroll 10
    for (int c = tid; c < H / 4; c += 128) {
        float4 wv = __ldcs(&wr[c]);
        float4 v0 = x0[c], v1 = x1[c];
        a0 += wv.x * v0.x + wv.y * v0.y + wv.z * v0.z + wv.w * v0.w;
        a1 += wv.x * v1.x + wv.y * v1.y + wv.z * v1.z + wv.w * v1.w;
    }
    a0 = warp_sum(a0); a1 = warp_sum(a1);
    __shared__ float r0[4], r1[4];
    int lane = tid & 31, wid = tid >> 5;
    if (!lane) { r0[wid] = a0; r1[wid] = a1; }
    __syncthreads();
    if (tid == 0) g_qa[row]       = r0[0] + r0[1] + r0[2] + r0[3];
    if (tid == 1) g_qa[QLR + row] = r1[0] + r1[1] + r1[2] + r1[3];
}

// ---------------- RMSNorm(q_a) in place ----------------
__global__ void __launch_bounds__(512) rmsnorm_k(const float* __restrict__ lnw) {
    int b = blockIdx.x, tid = threadIdx.x;  // 512 threads
    float x[3]; float ss = 0.f;
    #pragma unroll
    for (int i = 0; i < 3; i++) { x[i] = g_qa[b * QLR + tid + i * 512]; ss += x[i] * x[i]; }
    __shared__ float red[512];
    red[tid] = ss; __syncthreads();
    for (int s = 256; s; s >>= 1) { if (tid < s) red[tid] += red[tid + s]; __syncthreads(); }
    float inv = rsqrtf(red[0] / (float)QLR + 1e-6f);
    #pragma unroll
    for (int i = 0; i < 3; i++)
        g_qa[b * QLR + tid + i * 512] = x[i] * inv * lnw[tid + i * 512];
}

// ------- q = q_a @ q_b_w^T : persistent, 1 row/warp (86% balance) -- ncu slot -------
__global__ void __launch_bounds__(128, 12) qb_gemv(const float* __restrict__ w) {
    int lane = threadIdx.x & 31;
    int wgid = (blockIdx.x * 4) + (threadIdx.x >> 5);   // 0..PWARPS-1
    const float4* x0 = (const float4*)g_qa;
    const float4* x1 = (const float4*)(g_qa + QLR);
    for (int row = wgid; row < NH * DQ; row += PWARPS) {
        const float4* wr = (const float4*)(w + (size_t)row * QLR);
        float a0 = 0.f, a1 = 0.f;
        #pragma unroll 6
        for (int c = lane; c < QLR / 4; c += 32) {      // 12 iterations
            float4 wv = __ldcs(&wr[c]);
            float4 v0 = x0[c], v1 = x1[c];
            a0 += wv.x * v0.x + wv.y * v0.y + wv.z * v0.z + wv.w * v0.w;
            a1 += wv.x * v1.x + wv.y * v1.y + wv.z * v1.z + wv.w * v1.w;
        }
        a0 = warp_sum(a0); a1 = warp_sum(a1);
        if (!lane) { g_q[row] = a0; g_q[NH * DQ + row] = a1; }
    }
}

// ---------------- RoPE on q_pe (position KV-1) ----------------
__global__ void __launch_bounds__(256) rope_q_kernel(int KV) {
    int idx = blockIdx.x * 256 + threadIdx.x;
    if (idx >= 2 * NH * 32) return;
    int i = idx & 31;
    int h = (idx >> 5) % NH;
    int b = idx / (NH * 32);
    float ifr = exp2f(-LOG2_THETA * (float)(2 * i) / 64.0f);
    float s, c; __sincosf((float)(KV - 1) * ifr, &s, &c);
    float x0 = g_q[b * NH * DQ + h * DQ + DN + 2 * i];
    float x1 = g_q[b * NH * DQ + h * DQ + DN + 2 * i + 1];
    g_qpe[(b * NH + h) * DR + 2 * i]     = x0 * c - x1 * s;
    g_qpe[(b * NH + h) * DR + 2 * i + 1] = x0 * s + x1 * c;
}

// ---------------- q_abs[b,h,c] = sum_d q_nope[b,h,d] * kv_b_w[h*256+d, c] ----------------
__global__ void __launch_bounds__(512) qabs_kernel(const float* __restrict__ kvb) {
    int h = blockIdx.x;          // 128 blocks
    int c = threadIdx.x;         // 512 threads
    __shared__ float qn[2][DN];
    if (c < 256) qn[c >> 7][c & 127] = g_q[(c >> 7) * NH * DQ + h * DQ + (c & 127)];
    __syncthreads();
    const float* wp = kvb + (size_t)(h * 256) * KVLR + c;
    float a0 = 0.f, a1 = 0.f;
    #pragma unroll 16
    for (int d = 0; d < DN; d++) {
        float w = __ldcs(&wp[(size_t)d * KVLR]);
        a0 += qn[0][d] * w;
        a1 += qn[1][d] * w;
    }
    g_qabs[h * KVLR + c] = a0;
    g_qabs[NH * KVLR + h * KVLR + c] = a1;
}

// ---------------- scores[b,h,k] = (q_abs·c_kv + q_pe·k_pe) * scale ----------------
__global__ void __launch_bounds__(256) scores_kernel(const float* __restrict__ ckv, int KV) {
    __shared__ float Qs[32][66];
    __shared__ float KsT[64][130];
    int b = blockIdx.z, h0 = blockIdx.y * 32, k0 = blockIdx.x * 128;
    int tid = threadIdx.x, lane = tid & 31, wid = tid >> 5;
    unsigned long long acc[4][2] = {};
    for (int chunk = 0; chunk < 9; chunk++) {
        if (chunk < 8) {
            int c0 = chunk * 64;
            #pragma unroll
            for (int t = tid; t < 32 * 16; t += 256) {
                int r = t >> 4, c4 = t & 15;
                float4 v = *(const float4*)&g_qabs[((b * NH) + h0 + r) * KVLR + c0 + c4 * 4];
                Qs[r][c4*4+0] = v.x; Qs[r][c4*4+1] = v.y; Qs[r][c4*4+2] = v.z; Qs[r][c4*4+3] = v.w;
            }
            int c = tid & 63, kk = tid >> 6;
            #pragma unroll 8
            for (int kq = 0; kq < 32; kq++) {
                int k = kq * 4 + kk;
                KsT[c][k] = ckv[((size_t)b * KV + k0 + k) * KVLR + c0 + c];
            }
        } else {
            #pragma unroll
            for (int t = tid; t < 32 * 16; t += 256) {
                int r = t >> 4, c4 = t & 15;
                float4 v = *(const float4*)&g_qpe[((b * NH) + h0 + r) * DR + c4 * 4];
                Qs[r][c4*4+0] = v.x; Qs[r][c4*4+1] = v.y; Qs[r][c4*4+2] = v.z; Qs[r][c4*4+3] = v.w;
            }
            int c = tid & 63, kk = tid >> 6;
            #pragma unroll 8
            for (int kq = 0; kq < 32; kq++) {
                int k = kq * 4 + kk;
                KsT[c][k] = g_kpe[((size_t)b * KV + k0 + k) * DR + c];
            }
        }
        __syncthreads();
        #pragma unroll 8
        for (int cc = 0; cc < 64; cc++) {
            unsigned long long kA = *(const unsigned long long*)&KsT[cc][lane * 2];
            unsigned long long kB = *(const unsigned long long*)&KsT[cc][lane * 2 + 64];
            #pragma unroll
            for (int i = 0; i < 4; i++) {
                float q = Qs[wid + 8 * i][cc];
                unsigned long long qq = pack2(q, q);
                ffma2(acc[i][0], qq, kA);
                ffma2(acc[i][1], qq, kB);
            }
        }
        __syncthreads();
    }
    const float sc = rsqrtf((float)DQ);
    #pragma unroll
    for (int i = 0; i < 4; i++) {
        #pragma unroll
        for (int jj = 0; jj < 2; jj++) {
            float lo, hi; unpack2(acc[i][jj], lo, hi);
            float2 v = make_float2(lo * sc, hi * sc);
            *(float2*)&g_scores[(size_t)(b * NH + h0 + wid + 8 * i) * KV + k0 + lane * 2 + 64 * jj] = v;
        }
    }
}

// ---------------- softmax over k ----------------
__global__ void __launch_bounds__(256) softmax_kernel(int KV) {
    int bh = blockIdx.x;
    float* s = g_scores + (size_t)bh * KV;
    int tid = threadIdx.x;  // 256
    int n = KV >> 8;
    float v[8];
    float m = -1e30f;
    for (int i = 0; i < n; i++) { v[i] = s[tid + i * 256]; m = fmaxf(m, v[i]); }
    __shared__ float red[256];
    red[tid] = m; __syncthreads();
    for (int st = 128; st; st >>= 1) { if (tid < st) red[tid] = fmaxf(red[tid], red[tid + st]); __syncthreads(); }
    m = red[0]; __syncthreads();
    float sum = 0.f;
    for (int i = 0; i < n; i++) { v[i] = __expf(v[i] - m); sum += v[i]; }
    red[tid] = sum; __syncthreads();
    for (int st = 128; st; st >>= 1) { if (tid < st) red[tid] += red[tid + st]; __syncthreads(); }
    float inv = 1.f / red[0];
    for (int i = 0; i < n; i++) s[tid + i * 256] = v[i] * inv;
}

// ---------------- partial attn·c_kv (split-K = 4), FFMA2-packed ----------------
__global__ void __launch_bounds__(256) actv_kernel(const float* __restrict__ ckv, int KV) {
    __shared__ float As[32][68];
    __shared__ float Bs[64][128];
    int c0 = blockIdx.x * 128, h0 = blockIdx.y * 32;
    int b = blockIdx.z >> 2, sp = blockIdx.z & 3;
    int kbeg = sp * (KV / 4);
    int tid = threadIdx.x, lane = tid & 31, wid = tid >> 5;
    unsigned long long acc[4][2] = {};
    for (int kc0 = kbeg; kc0 < kbeg + KV / 4; kc0 += 64) {
        #pragma unroll
        for (int t = tid; t < 32 * 16; t += 256) {
            int r = t >> 4, c4 = t & 15;
            float4 v = *(const float4*)&g_scores[(size_t)(b * NH + h0 + r) * KV + kc0 + c4 * 4];
            *(float4*)&As[r][c4 * 4] = v;
        }
        #pragma unroll
        for (int t = tid; t < 64 * 32; t += 256) {
            int r = t >> 5, c4 = t & 31;
            *(float4*)&Bs[r][c4 * 4] =
                *(const float4*)&ckv[((size_t)b * KV + kc0 + r) * KVLR + c0 + c4 * 4];
        }
        __syncthreads();
        #pragma unroll 8
        for (int kc = 0; kc < 64; kc++) {
            unsigned long long b0 = *(const unsigned long long*)&Bs[kc][lane * 4];
            unsigned long long b1 = *(const unsigned long long*)&Bs[kc][lane * 4 + 2];
            #pragma unroll
            for (int i = 0; i < 4; i++) {
                float a = As[wid + 8 * i][kc];
                unsigned long long aa = pack2(a, a);
                ffma2(acc[i][0], aa, b0);
                ffma2(acc[i][1], aa, b1);
            }
        }
        __syncthreads();
    }
    #pragma unroll
    for (int i = 0; i < 4; i++) {
        float x0, x1, x2, x3;
        unpack2(acc[i][0], x0, x1);
        unpack2(acc[i][1], x2, x3);
        float4 v = make_float4(x0, x1, x2, x3);
        *(float4*)&g_part[sp][(size_t)(b * NH + h0 + wid + 8 * i) * KVLR + c0 + lane * 4] = v;
    }
}

// ---------------- out_v: grid 1024 = (h, dv-eighth), 256 thr, warp = 2 dv rows ----------------
__global__ void __launch_bounds__(256) outv_kernel(const float* __restrict__ kvb) {
    int h = blockIdx.x >> 3, dvE = blockIdx.x & 7;
    __shared__ float as[2][KVLR];
    int tid = threadIdx.x;            // 256
    for (int t = tid; t < 2 * KVLR; t += 256) {
        int b = t >> 9, c = t & 511;
        float v = 0.f;
        #pragma unroll
        for (int sp = 0; sp < 4; sp++) v += g_part[sp][(size_t)(b * NH + h) * KVLR + c];
        as[b][c] = v;
    }
    __syncthreads();
    int lane = tid & 31, wid = tid >> 5;
    int dv0 = dvE * 16 + wid * 2;                 // 2 consecutive dv rows per warp
    const float4* wp0 = (const float4*)(kvb + (size_t)(h * 256 + 128 + dv0 + 0) * KVLR);
    const float4* wp1 = (const float4*)(kvb + (size_t)(h * 256 + 128 + dv0 + 1) * KVLR);
    float a0[2] = {0.f, 0.f};
    float a1[2] = {0.f, 0.f};
    #pragma unroll
    for (int c4 = lane; c4 < KVLR / 4; c4 += 32) {   // 4 iterations
        float4 w0 = __ldcs(&wp0[c4]);
        float4 w1 = __ldcs(&wp1[c4]);
        float4 v0 = *(const float4*)&as[0][c4 * 4];
        float4 v1 = *(const float4*)&as[1][c4 * 4];
        a0[0] += w0.x*v0.x + w0.y*v0.y + w0.z*v0.z + w0.w*v0.w;
        a1[0] += w0.x*v1.x + w0.y*v1.y + w0.z*v1.z + w0.w*v1.w;
        a0[1] += w1.x*v0.x + w1.y*v0.y + w1.z*v0.z + w1.w*v0.w;
        a1[1] += w1.x*v1.x + w1.y*v1.y + w1.z*v1.z + w1.w*v1.w;
    }
    #pragma unroll
    for (int r = 0; r < 2; r++) {
        a0[r] = warp_sum(a0[r]);
        a1[r] = warp_sum(a1[r]);
    }
    if (!lane) {
        #pragma unroll
        for (int r = 0; r < 2; r++) {
            g_outv[h * DV + dv0 + r] = a0[r];
            g_outv[NH * DV + h * DV + dv0 + r] = a1[r];
        }
    }
}

// ------- o_proj stage 1: persistent, task = (row, sixteenth of K) -> partials -------
__global__ void __launch_bounds__(128, 12) oproj_part(const float* __restrict__ ow) {
    int lane = threadIdx.x & 31;
    int wgid = (blockIdx.x * 4) + (threadIdx.x >> 5);
    const int NT = H * 16;                         // 81920 tasks
    const float4* x0 = (const float4*)g_outv;
    const float4* x1 = (const float4*)(g_outv + NH * DV);
    for (int t = wgid; t < NT; t += PWARPS) {
        int row = t >> 4, six = t & 15;
        int cbase = six * 256;                     // float4 offset: 256 float4 = 1024 floats
        const float4* wr = (const float4*)(ow + (size_t)row * (NH * DV)) + cbase;
        const float4* p0 = x0 + cbase;
        const float4* p1 = x1 + cbase;
        float a0 = 0.f, a1 = 0.f;
        #pragma unroll
        for (int c = lane; c < 256; c += 32) {     // 8 iterations
            float4 wv = __ldcs(&wr[c]);
            float4 v0 = p0[c], v1 = p1[c];
            a0 += wv.x * v0.x + wv.y * v0.y + wv.z * v0.z + wv.w * v0.w;
            a1 += wv.x * v1.x + wv.y * v1.y + wv.z * v1.z + wv.w * v1.w;
        }
        a0 = warp_sum(a0); a1 = warp_sum(a1);
        if (!lane) { g_opart0[t] = a0; g_opart1[t] = a1; }
    }
}

// ------- o_proj stage 2: combine 16 partials per output -------
__global__ void __launch_bounds__(128) oproj_combine(float* __restrict__ out) {
    int idx = blockIdx.x * 128 + threadIdx.x;      // 0..2*H-1
    if (idx >= 2 * H) return;
    int b = idx >= H;
    int row = b ? (idx - H) : idx;
    const float4* p = (const float4*)((b ? g_opart1 : g_opart0) + row * 16);
    float s = 0.f;
    #pragma unroll
    for (int q = 0; q < 4; q++) {
        float4 v = p[q];
        s += v.x + v.y + v.z + v.w;
    }
    out[idx] = s;
}

// ---------------- launch ----------------
extern "C" void kernel_launch(void* const* d_in, const int* in_sizes, int n_in,
                              void* d_out, int out_size) {
    const float* hidden = (const float*)d_in[0];
    const float* ckv    = (const float*)d_in[1];
    const float* kpe    = (const float*)d_in[2];
    const float* qaw    = (const float*)d_in[3];
    const float* lnw    = (const float*)d_in[4];
    const float* qbw    = (const float*)d_in[5];
    const float* kvb    = (const float*)d_in[6];
    const float* ow     = (const float*)d_in[7];
    float* out = (float*)d_out;

    int B  = in_sizes[0] / H;          // 2
    int KV = in_sizes[2] / (B * DR);   // 2048

    rope_k_kernel<<<(B * KV * 32 + 255) / 256, 256>>>(kpe, KV);   // 1
    qa_gemv<<<QLR, 128>>>(hidden, qaw);                           // 2
    rmsnorm_k<<<B, 512>>>(lnw);                                   // 3
    qb_gemv<<<PBLOCKS, 128>>>(qbw);                               // 4  <- ncu slot
    rope_q_kernel<<<(B * NH * 32 + 255) / 256, 256>>>(KV);        // 5
    qabs_kernel<<<NH, 512>>>(kvb);                                // 6
    scores_kernel<<<dim3(KV / 128, NH / 32, B), 256>>>(ckv, KV);  // 7
    softmax_kernel<<<B * NH, 256>>>(KV);                          // 8
    actv_kernel<<<dim3(KVLR / 128, NH / 32, B * 4), 256>>>(ckv, KV); // 9
    outv_kernel<<<NH * 8, 256>>>(kvb);                            // 10
    oproj_part<<<PBLOCKS, 128>>>(ow);                             // 11
    oproj_combine<<<(2 * H + 127) / 128, 128>>>(out);             // 12
}